// round 1
// baseline (speedup 1.0000x reference)
#include <cuda_runtime.h>
#include <cstdint>

#define HID 128
#define NMAX 100000

// Scratch (allowed: __device__ globals, no runtime allocation)
__device__ float g_buf0[(size_t)NMAX * HID];  // xw1, then hw2
__device__ float g_h   [(size_t)NMAX * HID];  // layer-1 aggregate
__device__ float g_z   [(size_t)NMAX * HID];  // layer-2 aggregate

// ---------------------------------------------------------------------------
// GEMM: Y[n,128] = (relu_in ? relu(X) : X)[n,128] @ W[128,128]
// 64-row tiles, W chunked 64x128 in smem, per-thread 4 rows x 8 cols.
// ---------------------------------------------------------------------------
__global__ __launch_bounds__(256) void gemm_kernel(
    const float* __restrict__ X, const float* __restrict__ W,
    float* __restrict__ Y, int n, int relu_in)
{
    __shared__ float Ws[64][HID];   // 32 KB chunk: W rows [kc, kc+64)

    const int tx = threadIdx.x & 15;   // col group: 8 cols each
    const int ty = threadIdx.x >> 4;   // row group: 4 rows each
    const int row0 = blockIdx.x * 64 + ty * 4;

    // Clamped row pointers: OOB rows read row 0 safely, store is guarded.
    const float* xp[4];
#pragma unroll
    for (int i = 0; i < 4; i++) {
        int r = row0 + i;
        int rc = r < n ? r : 0;
        xp[i] = X + (size_t)rc * HID;
    }

    float acc[4][8];
#pragma unroll
    for (int i = 0; i < 4; i++)
#pragma unroll
        for (int j = 0; j < 8; j++) acc[i][j] = 0.f;

    for (int kc = 0; kc < HID; kc += 64) {
        __syncthreads();
        // Stage W chunk: 64x128 floats = 2048 float4, 8 per thread
        for (int i = threadIdx.x; i < 64 * 32; i += 256) {
            int r = i >> 5, c4 = i & 31;
            ((float4*)&Ws[r][0])[c4] =
                __ldg((const float4*)(W + (size_t)(kc + r) * HID) + c4);
        }
        __syncthreads();

#pragma unroll 4
        for (int k4 = 0; k4 < 64; k4 += 4) {
            float av[4][4];
#pragma unroll
            for (int i = 0; i < 4; i++) {
                float4 t = __ldg((const float4*)(xp[i] + kc + k4));
                if (relu_in) {
                    t.x = fmaxf(t.x, 0.f); t.y = fmaxf(t.y, 0.f);
                    t.z = fmaxf(t.z, 0.f); t.w = fmaxf(t.w, 0.f);
                }
                av[i][0] = t.x; av[i][1] = t.y; av[i][2] = t.z; av[i][3] = t.w;
            }
#pragma unroll
            for (int j = 0; j < 4; j++) {
                int k = k4 + j;
                float4 b0 = ((float4*)&Ws[k][0])[tx * 2];
                float4 b1 = ((float4*)&Ws[k][0])[tx * 2 + 1];
#pragma unroll
                for (int i = 0; i < 4; i++) {
                    float a = av[i][j];
                    acc[i][0] += a * b0.x; acc[i][1] += a * b0.y;
                    acc[i][2] += a * b0.z; acc[i][3] += a * b0.w;
                    acc[i][4] += a * b1.x; acc[i][5] += a * b1.y;
                    acc[i][6] += a * b1.z; acc[i][7] += a * b1.w;
                }
            }
        }
    }

#pragma unroll
    for (int i = 0; i < 4; i++) {
        int r = row0 + i;
        if (r < n) {
            float4 o0 = make_float4(acc[i][0], acc[i][1], acc[i][2], acc[i][3]);
            float4 o1 = make_float4(acc[i][4], acc[i][5], acc[i][6], acc[i][7]);
            float4* yp = (float4*)(Y + (size_t)r * HID + tx * 8);
            yp[0] = o0; yp[1] = o1;
        }
    }
}

// ---------------------------------------------------------------------------
// Scatter: out[dst] += w_e * F[src], one warp per edge, lane = one float4.
// red.global.add.v4.f32 -> REDG, no return trip.
// ---------------------------------------------------------------------------
__global__ __launch_bounds__(256) void scatter_kernel(
    const float* __restrict__ F, const int* __restrict__ ei,
    const float* __restrict__ ew, float* __restrict__ out, int E)
{
    long long t = (long long)blockIdx.x * blockDim.x + threadIdx.x;
    int e = (int)(t >> 5);
    if (e >= E) return;
    int lane = (int)(t & 31);

    int   s = __ldg(ei + e);
    int   d = __ldg(ei + E + e);
    float w = __ldg(ew + e);

    float4 v = __ldg((const float4*)(F + (size_t)s * HID) + lane);
    v.x *= w; v.y *= w; v.z *= w; v.w *= w;

    float* p = out + (size_t)d * HID + lane * 4;
    asm volatile("red.global.add.v4.f32 [%0], {%1,%2,%3,%4};"
                 :: "l"(p), "f"(v.x), "f"(v.y), "f"(v.z), "f"(v.w)
                 : "memory");
}

// ---------------------------------------------------------------------------
// Pair epilogue: out[p,:] = Wlin @ concat(z[a], z[b]); one warp per pair.
// ---------------------------------------------------------------------------
__global__ __launch_bounds__(256) void pair_kernel(
    const float* __restrict__ Z, const int* __restrict__ pe,
    const float* __restrict__ Wlin, float* __restrict__ out, int P)
{
    __shared__ float4 wl[128];   // Wlin [2][256] = 128 float4
    for (int i = threadIdx.x; i < 128; i += 256)
        wl[i] = __ldg((const float4*)Wlin + i);
    __syncthreads();

    long long t = (long long)blockIdx.x * blockDim.x + threadIdx.x;
    int p = (int)(t >> 5);
    if (p >= P) return;
    int lane = (int)(t & 31);

    int a = __ldg(pe + p);
    int b = __ldg(pe + P + p);

    float4 za = __ldg((const float4*)(Z + (size_t)a * HID) + lane);
    float4 zb = __ldg((const float4*)(Z + (size_t)b * HID) + lane);

    float4 w0a = wl[lane];        // Wlin[0][lane*4 ..]
    float4 w0b = wl[32 + lane];   // Wlin[0][128 + lane*4 ..]
    float4 w1a = wl[64 + lane];   // Wlin[1][lane*4 ..]
    float4 w1b = wl[96 + lane];   // Wlin[1][128 + lane*4 ..]

    float acc0 = za.x * w0a.x + za.y * w0a.y + za.z * w0a.z + za.w * w0a.w
               + zb.x * w0b.x + zb.y * w0b.y + zb.z * w0b.z + zb.w * w0b.w;
    float acc1 = za.x * w1a.x + za.y * w1a.y + za.z * w1a.z + za.w * w1a.w
               + zb.x * w1b.x + zb.y * w1b.y + zb.z * w1b.z + zb.w * w1b.w;

#pragma unroll
    for (int o = 16; o > 0; o >>= 1) {
        acc0 += __shfl_xor_sync(0xFFFFFFFFu, acc0, o);
        acc1 += __shfl_xor_sync(0xFFFFFFFFu, acc1, o);
    }
    if (lane == 0) {
        out[(size_t)p * 2]     = acc0;
        out[(size_t)p * 2 + 1] = acc1;
    }
}

// ---------------------------------------------------------------------------
// Launch
// Inputs: 0:x 1:edge_index1 2:edge_index2 3:edge_weight1 4:edge_weight2
//         5:pos_edge_index 6:W1 7:W2 8:Wlin      out: [P,2] float
// ---------------------------------------------------------------------------
extern "C" void kernel_launch(void* const* d_in, const int* in_sizes, int n_in,
                              void* d_out, int out_size)
{
    const float* x    = (const float*)d_in[0];
    const int*   ei1  = (const int*)  d_in[1];
    const int*   ei2  = (const int*)  d_in[2];
    const float* ew1  = (const float*)d_in[3];
    const float* ew2  = (const float*)d_in[4];
    const int*   pe   = (const int*)  d_in[5];
    const float* W1   = (const float*)d_in[6];
    const float* W2   = (const float*)d_in[7];
    const float* Wlin = (const float*)d_in[8];
    float* out = (float*)d_out;

    int n  = in_sizes[0] / HID;
    int E1 = in_sizes[3];
    int E2 = in_sizes[4];
    int P  = in_sizes[5] / 2;

    void *p_buf0, *p_h, *p_z;
    cudaGetSymbolAddress(&p_buf0, g_buf0);
    cudaGetSymbolAddress(&p_h,    g_h);
    cudaGetSymbolAddress(&p_z,    g_z);
    float* buf0 = (float*)p_buf0;
    float* h    = (float*)p_h;
    float* z    = (float*)p_z;

    size_t featBytes = (size_t)n * HID * sizeof(float);
    cudaMemsetAsync(h, 0, featBytes);
    cudaMemsetAsync(z, 0, featBytes);

    int gemmBlocks = (n + 63) / 64;

    // Layer 1: xw1 = x @ W1 ; h = scatter-add
    gemm_kernel<<<gemmBlocks, 256>>>(x, W1, buf0, n, 0);
    {
        long long th = (long long)E1 * 32;
        int blocks = (int)((th + 255) / 256);
        scatter_kernel<<<blocks, 256>>>(buf0, ei1, ew1, h, E1);
    }

    // Layer 2: hw2 = relu(h) @ W2 ; z = scatter-add
    gemm_kernel<<<gemmBlocks, 256>>>(h, W2, buf0, n, 1);
    {
        long long th = (long long)E2 * 32;
        int blocks = (int)((th + 255) / 256);
        scatter_kernel<<<blocks, 256>>>(buf0, ei2, ew2, z, E2);
    }

    // Pair epilogue
    {
        long long th = (long long)P * 32;
        int blocks = (int)((th + 255) / 256);
        pair_kernel<<<blocks, 256>>>(z, pe, Wlin, out, P);
    }
}

// round 2
// speedup vs baseline: 1.0438x; 1.0438x over previous
#include <cuda_runtime.h>
#include <cstdint>

#define HID 128
#define NMAX 100000

// Scratch (allowed: __device__ globals, no runtime allocation)
__device__ float g_buf0[(size_t)NMAX * HID];  // xw1, then hw2
__device__ float g_h   [(size_t)NMAX * HID];  // layer-1 aggregate
__device__ float g_z   [(size_t)NMAX * HID];  // layer-2 aggregate

// Packed fp32x2 helpers (Blackwell FFMA2 — only reachable via PTX)
__device__ __forceinline__ void ffma2(unsigned long long& acc,
                                      unsigned long long a,
                                      unsigned long long b) {
    asm("fma.rn.f32x2 %0, %1, %2, %0;" : "+l"(acc) : "l"(a), "l"(b));
}
__device__ __forceinline__ unsigned long long pack_dup(float a) {
    unsigned long long r;
    asm("mov.b64 %0, {%1, %1};" : "=l"(r) : "r"(__float_as_uint(a)));
    return r;
}
__device__ __forceinline__ float2 unpack2(unsigned long long v) {
    float2 f;
    asm("mov.b64 {%0, %1}, %2;" : "=f"(f.x), "=f"(f.y) : "l"(v));
    return f;
}

// ---------------------------------------------------------------------------
// GEMM: Y[n,128] = (RELU ? relu(X) : X)[n,128] @ W[128,128]
// 64-row tiles, W chunked 64x128 in smem, per-thread 4 rows x 8 cols,
// FFMA2 packed math (columns paired).
// ---------------------------------------------------------------------------
template <int RELU>
__global__ __launch_bounds__(256) void gemm_kernel(
    const float* __restrict__ X, const float* __restrict__ W,
    float* __restrict__ Y, int n)
{
    __shared__ float Ws[64][HID];   // 32 KB chunk: W rows [kc, kc+64)

    const int tx = threadIdx.x & 15;   // col group: 8 cols each
    const int ty = threadIdx.x >> 4;   // row group: 4 rows each
    const int row0 = blockIdx.x * 64 + ty * 4;

    // Clamped row pointers: OOB rows read row 0 safely, store is guarded.
    const float* xp[4];
#pragma unroll
    for (int i = 0; i < 4; i++) {
        int r = row0 + i;
        int rc = r < n ? r : 0;
        xp[i] = X + (size_t)rc * HID;
    }

    unsigned long long acc[4][4];   // 4 rows x 4 col-pairs (8 cols)
#pragma unroll
    for (int i = 0; i < 4; i++)
#pragma unroll
        for (int j = 0; j < 4; j++) acc[i][j] = 0ULL;

    for (int kc = 0; kc < HID; kc += 64) {
        __syncthreads();
        // Stage W chunk: 64x128 floats = 2048 float4, 8 per thread
        for (int i = threadIdx.x; i < 64 * 32; i += 256) {
            int r = i >> 5, c4 = i & 31;
            ((float4*)&Ws[r][0])[c4] =
                __ldg((const float4*)(W + (size_t)(kc + r) * HID) + c4);
        }
        __syncthreads();

#pragma unroll 4
        for (int k4 = 0; k4 < 64; k4 += 4) {
            float av[4][4];
#pragma unroll
            for (int i = 0; i < 4; i++) {
                float4 t = __ldg((const float4*)(xp[i] + kc + k4));
                if (RELU) {
                    t.x = fmaxf(t.x, 0.f); t.y = fmaxf(t.y, 0.f);
                    t.z = fmaxf(t.z, 0.f); t.w = fmaxf(t.w, 0.f);
                }
                av[i][0] = t.x; av[i][1] = t.y; av[i][2] = t.z; av[i][3] = t.w;
            }
#pragma unroll
            for (int j = 0; j < 4; j++) {
                int k = k4 + j;
                // 8 cols = 4 packed pairs, 16B-aligned shared loads
                ulonglong2 b01 = *(const ulonglong2*)&Ws[k][tx * 8];
                ulonglong2 b23 = *(const ulonglong2*)&Ws[k][tx * 8 + 4];
#pragma unroll
                for (int i = 0; i < 4; i++) {
                    unsigned long long aa = pack_dup(av[i][j]);
                    ffma2(acc[i][0], aa, b01.x);
                    ffma2(acc[i][1], aa, b01.y);
                    ffma2(acc[i][2], aa, b23.x);
                    ffma2(acc[i][3], aa, b23.y);
                }
            }
        }
    }

#pragma unroll
    for (int i = 0; i < 4; i++) {
        int r = row0 + i;
        if (r < n) {
            float2 p0 = unpack2(acc[i][0]);
            float2 p1 = unpack2(acc[i][1]);
            float2 p2 = unpack2(acc[i][2]);
            float2 p3 = unpack2(acc[i][3]);
            float4* yp = (float4*)(Y + (size_t)r * HID + tx * 8);
            yp[0] = make_float4(p0.x, p0.y, p1.x, p1.y);
            yp[1] = make_float4(p2.x, p2.y, p3.x, p3.y);
        }
    }
}

// ---------------------------------------------------------------------------
// Scatter: out[dst] += w_e * F[src]. One warp per 4 edges (MLP=4):
// vector index/weight broadcast loads, 4 independent gathers in flight,
// then 4 red.global.add.v4.f32 (REDG, no return trip).
// ---------------------------------------------------------------------------
__global__ __launch_bounds__(256) void scatter_kernel(
    const float* __restrict__ F, const int* __restrict__ ei,
    const float* __restrict__ ew, float* __restrict__ out, int E)
{
    int warp = (int)(((long long)blockIdx.x * blockDim.x + threadIdx.x) >> 5);
    int lane = threadIdx.x & 31;
    int e0 = warp * 4;
    if (e0 >= E) return;

    if (e0 + 4 <= E) {
        int4   s4 = __ldg((const int4*)ei + (e0 >> 2));
        int4   d4 = __ldg((const int4*)(ei + E) + (e0 >> 2));
        float4 w4 = __ldg((const float4*)ew + (e0 >> 2));

        float4 v0 = __ldg((const float4*)(F + (size_t)s4.x * HID) + lane);
        float4 v1 = __ldg((const float4*)(F + (size_t)s4.y * HID) + lane);
        float4 v2 = __ldg((const float4*)(F + (size_t)s4.z * HID) + lane);
        float4 v3 = __ldg((const float4*)(F + (size_t)s4.w * HID) + lane);

        v0.x *= w4.x; v0.y *= w4.x; v0.z *= w4.x; v0.w *= w4.x;
        v1.x *= w4.y; v1.y *= w4.y; v1.z *= w4.y; v1.w *= w4.y;
        v2.x *= w4.z; v2.y *= w4.z; v2.z *= w4.z; v2.w *= w4.z;
        v3.x *= w4.w; v3.y *= w4.w; v3.z *= w4.w; v3.w *= w4.w;

        float* p0 = out + (size_t)d4.x * HID + lane * 4;
        float* p1 = out + (size_t)d4.y * HID + lane * 4;
        float* p2 = out + (size_t)d4.z * HID + lane * 4;
        float* p3 = out + (size_t)d4.w * HID + lane * 4;
        asm volatile("red.global.add.v4.f32 [%0], {%1,%2,%3,%4};"
                     :: "l"(p0), "f"(v0.x), "f"(v0.y), "f"(v0.z), "f"(v0.w) : "memory");
        asm volatile("red.global.add.v4.f32 [%0], {%1,%2,%3,%4};"
                     :: "l"(p1), "f"(v1.x), "f"(v1.y), "f"(v1.z), "f"(v1.w) : "memory");
        asm volatile("red.global.add.v4.f32 [%0], {%1,%2,%3,%4};"
                     :: "l"(p2), "f"(v2.x), "f"(v2.y), "f"(v2.z), "f"(v2.w) : "memory");
        asm volatile("red.global.add.v4.f32 [%0], {%1,%2,%3,%4};"
                     :: "l"(p3), "f"(v3.x), "f"(v3.y), "f"(v3.z), "f"(v3.w) : "memory");
    } else {
        for (int e = e0; e < E; e++) {
            int   s = __ldg(ei + e);
            int   d = __ldg(ei + E + e);
            float w = __ldg(ew + e);
            float4 v = __ldg((const float4*)(F + (size_t)s * HID) + lane);
            v.x *= w; v.y *= w; v.z *= w; v.w *= w;
            float* p = out + (size_t)d * HID + lane * 4;
            asm volatile("red.global.add.v4.f32 [%0], {%1,%2,%3,%4};"
                         :: "l"(p), "f"(v.x), "f"(v.y), "f"(v.z), "f"(v.w) : "memory");
        }
    }
}

// ---------------------------------------------------------------------------
// Pair epilogue: out[p,:] = Wlin @ concat(z[a], z[b]); one warp per pair.
// ---------------------------------------------------------------------------
__global__ __launch_bounds__(256) void pair_kernel(
    const float* __restrict__ Z, const int* __restrict__ pe,
    const float* __restrict__ Wlin, float* __restrict__ out, int P)
{
    __shared__ float4 wl[128];   // Wlin [2][256] = 128 float4
    for (int i = threadIdx.x; i < 128; i += 256)
        wl[i] = __ldg((const float4*)Wlin + i);
    __syncthreads();

    long long t = (long long)blockIdx.x * blockDim.x + threadIdx.x;
    int p = (int)(t >> 5);
    if (p >= P) return;
    int lane = (int)(t & 31);

    int a = __ldg(pe + p);
    int b = __ldg(pe + P + p);

    float4 za = __ldg((const float4*)(Z + (size_t)a * HID) + lane);
    float4 zb = __ldg((const float4*)(Z + (size_t)b * HID) + lane);

    float4 w0a = wl[lane];        // Wlin[0][lane*4 ..]
    float4 w0b = wl[32 + lane];   // Wlin[0][128 + lane*4 ..]
    float4 w1a = wl[64 + lane];   // Wlin[1][lane*4 ..]
    float4 w1b = wl[96 + lane];   // Wlin[1][128 + lane*4 ..]

    float acc0 = za.x * w0a.x + za.y * w0a.y + za.z * w0a.z + za.w * w0a.w
               + zb.x * w0b.x + zb.y * w0b.y + zb.z * w0b.z + zb.w * w0b.w;
    float acc1 = za.x * w1a.x + za.y * w1a.y + za.z * w1a.z + za.w * w1a.w
               + zb.x * w1b.x + zb.y * w1b.y + zb.z * w1b.z + zb.w * w1b.w;

#pragma unroll
    for (int o = 16; o > 0; o >>= 1) {
        acc0 += __shfl_xor_sync(0xFFFFFFFFu, acc0, o);
        acc1 += __shfl_xor_sync(0xFFFFFFFFu, acc1, o);
    }
    if (lane == 0) {
        out[(size_t)p * 2]     = acc0;
        out[(size_t)p * 2 + 1] = acc1;
    }
}

// ---------------------------------------------------------------------------
// Launch
// Inputs: 0:x 1:edge_index1 2:edge_index2 3:edge_weight1 4:edge_weight2
//         5:pos_edge_index 6:W1 7:W2 8:Wlin      out: [P,2] float
// ---------------------------------------------------------------------------
extern "C" void kernel_launch(void* const* d_in, const int* in_sizes, int n_in,
                              void* d_out, int out_size)
{
    const float* x    = (const float*)d_in[0];
    const int*   ei1  = (const int*)  d_in[1];
    const int*   ei2  = (const int*)  d_in[2];
    const float* ew1  = (const float*)d_in[3];
    const float* ew2  = (const float*)d_in[4];
    const int*   pe   = (const int*)  d_in[5];
    const float* W1   = (const float*)d_in[6];
    const float* W2   = (const float*)d_in[7];
    const float* Wlin = (const float*)d_in[8];
    float* out = (float*)d_out;

    int n  = in_sizes[0] / HID;
    int E1 = in_sizes[3];
    int E2 = in_sizes[4];
    int P  = in_sizes[5] / 2;

    void *p_buf0, *p_h, *p_z;
    cudaGetSymbolAddress(&p_buf0, g_buf0);
    cudaGetSymbolAddress(&p_h,    g_h);
    cudaGetSymbolAddress(&p_z,    g_z);
    float* buf0 = (float*)p_buf0;
    float* h    = (float*)p_h;
    float* z    = (float*)p_z;

    size_t featBytes = (size_t)n * HID * sizeof(float);
    cudaMemsetAsync(h, 0, featBytes);
    cudaMemsetAsync(z, 0, featBytes);

    int gemmBlocks = (n + 63) / 64;

    // Layer 1: xw1 = x @ W1 ; h = scatter-add
    gemm_kernel<0><<<gemmBlocks, 256>>>(x, W1, buf0, n);
    {
        int warps = (E1 + 3) / 4;
        int blocks = (warps * 32 + 255) / 256;
        scatter_kernel<<<blocks, 256>>>(buf0, ei1, ew1, h, E1);
    }

    // Layer 2: hw2 = relu(h) @ W2 ; z = scatter-add
    gemm_kernel<1><<<gemmBlocks, 256>>>(h, W2, buf0, n);
    {
        int warps = (E2 + 3) / 4;
        int blocks = (warps * 32 + 255) / 256;
        scatter_kernel<<<blocks, 256>>>(buf0, ei2, ew2, z, E2);
    }

    // Pair epilogue
    {
        int warps = P;
        int blocks = (warps * 32 + 255) / 256;
        pair_kernel<<<blocks, 256>>>(z, pe, Wlin, out, P);
    }
}

// round 3
// speedup vs baseline: 1.2547x; 1.2020x over previous
#include <cuda_runtime.h>
#include <cstdint>

#define HID 128
#define NMAX 100000

// Scratch (allowed: __device__ globals, no runtime allocation)
__device__ float g_buf0[(size_t)NMAX * HID];  // xw1, then hw2
__device__ float g_h   [(size_t)NMAX * HID];  // layer-1 aggregate
__device__ float g_z   [(size_t)NMAX * HID];  // layer-2 aggregate

// Packed fp32x2 helpers (Blackwell FFMA2 — only reachable via PTX)
__device__ __forceinline__ void ffma2(unsigned long long& acc,
                                      unsigned long long a,
                                      unsigned long long b) {
    asm("fma.rn.f32x2 %0, %1, %2, %0;" : "+l"(acc) : "l"(a), "l"(b));
}
__device__ __forceinline__ unsigned long long pack_dup(float a) {
    unsigned long long r;
    asm("mov.b64 %0, {%1, %1};" : "=l"(r) : "r"(__float_as_uint(a)));
    return r;
}
__device__ __forceinline__ float2 unpack2(unsigned long long v) {
    float2 f;
    asm("mov.b64 {%0, %1}, %2;" : "=f"(f.x), "=f"(f.y) : "l"(v));
    return f;
}

// ---------------------------------------------------------------------------
// GEMM v2: Y[n,128] = (RELU ? relu(X) : X) @ W[128,128]
// Block = 128 rows x 128 cols, 256 threads (16x16), 8x8 per thread.
// W fully smem-resident (64 KB, staged once). X staged in 32-k chunks,
// double-buffered, coalesced row copy, ReLU folded into staging.
// Inner loop: registers + smem only, FFMA2 packed math.
// ---------------------------------------------------------------------------
#define XS_STRIDE 36   // 32 k-floats padded to 36 (16B-aligned rows)

template <int RELU>
__global__ __launch_bounds__(256, 2) void gemm_kernel(
    const float* __restrict__ X, const float* __restrict__ W,
    float* __restrict__ Y, int n)
{
    extern __shared__ float sm[];
    float* Ws = sm;                       // [128][128]
    float* Xs = sm + HID * HID;           // [2][128][XS_STRIDE]

    const int t  = threadIdx.x;
    const int tx = t & 15;                // col group: 8 cols
    const int ty = t >> 4;                // row group: 8 rows
    const int row0 = blockIdx.x * 128;

    // Stage whole W once: 4096 float4
    for (int i = t; i < 128 * 32; i += 256) {
        int r = i >> 5, c = i & 31;
        *(float4*)(Ws + r * HID + c * 4) =
            __ldg((const float4*)(W + (size_t)r * HID) + c);
    }

    // X chunk staging: rows [row0,row0+128) x k [kc,kc+32), coalesced
#define STAGE_X(buf, kc)                                                      \
    {                                                                          \
        float* dst = Xs + (buf) * (128 * XS_STRIDE);                           \
        for (int i = t; i < 128 * 8; i += 256) {                               \
            int m = i >> 3, c4 = i & 7;                                        \
            int r = row0 + m;                                                  \
            int rc = r < n ? r : 0;                                            \
            float4 v = __ldg((const float4*)(X + (size_t)rc * HID + (kc)) + c4);\
            if (RELU) {                                                        \
                v.x = fmaxf(v.x, 0.f); v.y = fmaxf(v.y, 0.f);                  \
                v.z = fmaxf(v.z, 0.f); v.w = fmaxf(v.w, 0.f);                  \
            }                                                                  \
            *(float4*)(dst + m * XS_STRIDE + c4 * 4) = v;                      \
        }                                                                      \
    }

    STAGE_X(0, 0);

    unsigned long long acc[8][4];   // 8 rows x 4 col-pairs
#pragma unroll
    for (int i = 0; i < 8; i++)
#pragma unroll
        for (int j = 0; j < 4; j++) acc[i][j] = 0ULL;

    __syncthreads();

    for (int cb = 0; cb < 4; cb++) {
        if (cb < 3) STAGE_X((cb + 1) & 1, (cb + 1) * 32);

        const float* xb = Xs + (cb & 1) * (128 * XS_STRIDE);
        const int kbase = cb * 32;

#pragma unroll
        for (int k4 = 0; k4 < 8; k4++) {
            float4 Af[8];
#pragma unroll
            for (int i = 0; i < 8; i++)
                Af[i] = *(const float4*)(xb + (ty * 8 + i) * XS_STRIDE + k4 * 4);

#pragma unroll
            for (int j = 0; j < 4; j++) {
                const float* wk = Ws + (size_t)(kbase + k4 * 4 + j) * HID + tx * 8;
                ulonglong2 b01 = *(const ulonglong2*)wk;
                ulonglong2 b23 = *(const ulonglong2*)(wk + 4);
#pragma unroll
                for (int i = 0; i < 8; i++) {
                    float a = (j == 0) ? Af[i].x : (j == 1) ? Af[i].y
                            : (j == 2) ? Af[i].z : Af[i].w;
                    unsigned long long aa = pack_dup(a);
                    ffma2(acc[i][0], aa, b01.x);
                    ffma2(acc[i][1], aa, b01.y);
                    ffma2(acc[i][2], aa, b23.x);
                    ffma2(acc[i][3], aa, b23.y);
                }
            }
        }
        __syncthreads();
    }

#pragma unroll
    for (int i = 0; i < 8; i++) {
        int r = row0 + ty * 8 + i;
        if (r < n) {
            float2 p0 = unpack2(acc[i][0]);
            float2 p1 = unpack2(acc[i][1]);
            float2 p2 = unpack2(acc[i][2]);
            float2 p3 = unpack2(acc[i][3]);
            float4* yp = (float4*)(Y + (size_t)r * HID + tx * 8);
            yp[0] = make_float4(p0.x, p0.y, p1.x, p1.y);
            yp[1] = make_float4(p2.x, p2.y, p3.x, p3.y);
        }
    }
}

#define GEMM_SMEM_BYTES ((HID * HID + 2 * 128 * XS_STRIDE) * (int)sizeof(float))

// ---------------------------------------------------------------------------
// Scatter: out[dst] += w_e * F[src]. One warp per 4 edges (MLP=4),
// red.global.add.v4.f32 (REDG, no return trip).
// ---------------------------------------------------------------------------
__global__ __launch_bounds__(256) void scatter_kernel(
    const float* __restrict__ F, const int* __restrict__ ei,
    const float* __restrict__ ew, float* __restrict__ out, int E)
{
    int warp = (int)(((long long)blockIdx.x * blockDim.x + threadIdx.x) >> 5);
    int lane = threadIdx.x & 31;
    int e0 = warp * 4;
    if (e0 >= E) return;

    if (e0 + 4 <= E) {
        int4   s4 = __ldg((const int4*)ei + (e0 >> 2));
        int4   d4 = __ldg((const int4*)(ei + E) + (e0 >> 2));
        float4 w4 = __ldg((const float4*)ew + (e0 >> 2));

        float4 v0 = __ldg((const float4*)(F + (size_t)s4.x * HID) + lane);
        float4 v1 = __ldg((const float4*)(F + (size_t)s4.y * HID) + lane);
        float4 v2 = __ldg((const float4*)(F + (size_t)s4.z * HID) + lane);
        float4 v3 = __ldg((const float4*)(F + (size_t)s4.w * HID) + lane);

        v0.x *= w4.x; v0.y *= w4.x; v0.z *= w4.x; v0.w *= w4.x;
        v1.x *= w4.y; v1.y *= w4.y; v1.z *= w4.y; v1.w *= w4.y;
        v2.x *= w4.z; v2.y *= w4.z; v2.z *= w4.z; v2.w *= w4.z;
        v3.x *= w4.w; v3.y *= w4.w; v3.z *= w4.w; v3.w *= w4.w;

        float* p0 = out + (size_t)d4.x * HID + lane * 4;
        float* p1 = out + (size_t)d4.y * HID + lane * 4;
        float* p2 = out + (size_t)d4.z * HID + lane * 4;
        float* p3 = out + (size_t)d4.w * HID + lane * 4;
        asm volatile("red.global.add.v4.f32 [%0], {%1,%2,%3,%4};"
                     :: "l"(p0), "f"(v0.x), "f"(v0.y), "f"(v0.z), "f"(v0.w) : "memory");
        asm volatile("red.global.add.v4.f32 [%0], {%1,%2,%3,%4};"
                     :: "l"(p1), "f"(v1.x), "f"(v1.y), "f"(v1.z), "f"(v1.w) : "memory");
        asm volatile("red.global.add.v4.f32 [%0], {%1,%2,%3,%4};"
                     :: "l"(p2), "f"(v2.x), "f"(v2.y), "f"(v2.z), "f"(v2.w) : "memory");
        asm volatile("red.global.add.v4.f32 [%0], {%1,%2,%3,%4};"
                     :: "l"(p3), "f"(v3.x), "f"(v3.y), "f"(v3.z), "f"(v3.w) : "memory");
    } else {
        for (int e = e0; e < E; e++) {
            int   s = __ldg(ei + e);
            int   d = __ldg(ei + E + e);
            float w = __ldg(ew + e);
            float4 v = __ldg((const float4*)(F + (size_t)s * HID) + lane);
            v.x *= w; v.y *= w; v.z *= w; v.w *= w;
            float* p = out + (size_t)d * HID + lane * 4;
            asm volatile("red.global.add.v4.f32 [%0], {%1,%2,%3,%4};"
                         :: "l"(p), "f"(v.x), "f"(v.y), "f"(v.z), "f"(v.w) : "memory");
        }
    }
}

// ---------------------------------------------------------------------------
// Pair epilogue: out[p,:] = Wlin @ concat(z[a], z[b]); one warp per pair.
// ---------------------------------------------------------------------------
__global__ __launch_bounds__(256) void pair_kernel(
    const float* __restrict__ Z, const int* __restrict__ pe,
    const float* __restrict__ Wlin, float* __restrict__ out, int P)
{
    __shared__ float4 wl[128];   // Wlin [2][256] = 128 float4
    for (int i = threadIdx.x; i < 128; i += 256)
        wl[i] = __ldg((const float4*)Wlin + i);
    __syncthreads();

    long long t = (long long)blockIdx.x * blockDim.x + threadIdx.x;
    int p = (int)(t >> 5);
    if (p >= P) return;
    int lane = (int)(t & 31);

    int a = __ldg(pe + p);
    int b = __ldg(pe + P + p);

    float4 za = __ldg((const float4*)(Z + (size_t)a * HID) + lane);
    float4 zb = __ldg((const float4*)(Z + (size_t)b * HID) + lane);

    float4 w0a = wl[lane];
    float4 w0b = wl[32 + lane];
    float4 w1a = wl[64 + lane];
    float4 w1b = wl[96 + lane];

    float acc0 = za.x * w0a.x + za.y * w0a.y + za.z * w0a.z + za.w * w0a.w
               + zb.x * w0b.x + zb.y * w0b.y + zb.z * w0b.z + zb.w * w0b.w;
    float acc1 = za.x * w1a.x + za.y * w1a.y + za.z * w1a.z + za.w * w1a.w
               + zb.x * w1b.x + zb.y * w1b.y + zb.z * w1b.z + zb.w * w1b.w;

#pragma unroll
    for (int o = 16; o > 0; o >>= 1) {
        acc0 += __shfl_xor_sync(0xFFFFFFFFu, acc0, o);
        acc1 += __shfl_xor_sync(0xFFFFFFFFu, acc1, o);
    }
    if (lane == 0) {
        out[(size_t)p * 2]     = acc0;
        out[(size_t)p * 2 + 1] = acc1;
    }
}

// ---------------------------------------------------------------------------
// Launch
// Inputs: 0:x 1:edge_index1 2:edge_index2 3:edge_weight1 4:edge_weight2
//         5:pos_edge_index 6:W1 7:W2 8:Wlin      out: [P,2] float
// ---------------------------------------------------------------------------
extern "C" void kernel_launch(void* const* d_in, const int* in_sizes, int n_in,
                              void* d_out, int out_size)
{
    const float* x    = (const float*)d_in[0];
    const int*   ei1  = (const int*)  d_in[1];
    const int*   ei2  = (const int*)  d_in[2];
    const float* ew1  = (const float*)d_in[3];
    const float* ew2  = (const float*)d_in[4];
    const int*   pe   = (const int*)  d_in[5];
    const float* W1   = (const float*)d_in[6];
    const float* W2   = (const float*)d_in[7];
    const float* Wlin = (const float*)d_in[8];
    float* out = (float*)d_out;

    int n  = in_sizes[0] / HID;
    int E1 = in_sizes[3];
    int E2 = in_sizes[4];
    int P  = in_sizes[5] / 2;

    void *p_buf0, *p_h, *p_z;
    cudaGetSymbolAddress(&p_buf0, g_buf0);
    cudaGetSymbolAddress(&p_h,    g_h);
    cudaGetSymbolAddress(&p_z,    g_z);
    float* buf0 = (float*)p_buf0;
    float* h    = (float*)p_h;
    float* z    = (float*)p_z;

    cudaFuncSetAttribute(gemm_kernel<0>,
        cudaFuncAttributeMaxDynamicSharedMemorySize, GEMM_SMEM_BYTES);
    cudaFuncSetAttribute(gemm_kernel<1>,
        cudaFuncAttributeMaxDynamicSharedMemorySize, GEMM_SMEM_BYTES);

    size_t featBytes = (size_t)n * HID * sizeof(float);
    cudaMemsetAsync(h, 0, featBytes);
    cudaMemsetAsync(z, 0, featBytes);

    int gemmBlocks = (n + 127) / 128;

    // Layer 1: xw1 = x @ W1 ; h = scatter-add
    gemm_kernel<0><<<gemmBlocks, 256, GEMM_SMEM_BYTES>>>(x, W1, buf0, n);
    {
        int warps = (E1 + 3) / 4;
        int blocks = (warps * 32 + 255) / 256;
        scatter_kernel<<<blocks, 256>>>(buf0, ei1, ew1, h, E1);
    }

    // Layer 2: hw2 = relu(h) @ W2 ; z = scatter-add
    gemm_kernel<1><<<gemmBlocks, 256, GEMM_SMEM_BYTES>>>(h, W2, buf0, n);
    {
        int warps = (E2 + 3) / 4;
        int blocks = (warps * 32 + 255) / 256;
        scatter_kernel<<<blocks, 256>>>(buf0, ei2, ew2, z, E2);
    }

    // Pair epilogue
    {
        int warps = P;
        int blocks = (warps * 32 + 255) / 256;
        pair_kernel<<<blocks, 256>>>(z, pe, Wlin, out, P);
    }
}

// round 5
// speedup vs baseline: 1.2651x; 1.0083x over previous
#include <cuda_runtime.h>
#include <cuda_bf16.h>
#include <cstdint>

#define HID 128
#define NMAX 100000

// Scratch (allowed: __device__ globals, no runtime allocation)
__device__ float g_buf0[(size_t)NMAX * HID];  // xw1, then hw2
__device__ float g_h   [(size_t)NMAX * HID];  // layer-1 aggregate
__device__ float g_z   [(size_t)NMAX * HID];  // layer-2 aggregate

__device__ __forceinline__ uint32_t smem_u32(const void* p) {
    uint32_t a;
    asm("{ .reg .u64 t; cvta.to.shared.u64 t, %1; cvt.u32.u64 %0, t; }"
        : "=r"(a) : "l"(p));
    return a;
}

#define LDM_X4(r0, r1, r2, r3, a)                                             \
    asm volatile("ldmatrix.sync.aligned.m8n8.x4.shared.b16 {%0,%1,%2,%3}, [%4];" \
                 : "=r"(r0), "=r"(r1), "=r"(r2), "=r"(r3) : "r"(a))
#define LDM_X4T(r0, r1, r2, r3, a)                                            \
    asm volatile("ldmatrix.sync.aligned.m8n8.x4.trans.shared.b16 {%0,%1,%2,%3}, [%4];" \
                 : "=r"(r0), "=r"(r1), "=r"(r2), "=r"(r3) : "r"(a))
#define MMA_BF16(d, a, b)                                                     \
    asm volatile("mma.sync.aligned.m16n8k16.row.col.f32.bf16.bf16.f32 "       \
                 "{%0,%1,%2,%3}, {%4,%5,%6,%7}, {%8,%9}, {%0,%1,%2,%3};"      \
                 : "+f"((d)[0]), "+f"((d)[1]), "+f"((d)[2]), "+f"((d)[3])     \
                 : "r"((a)[0]), "r"((a)[1]), "r"((a)[2]), "r"((a)[3]),        \
                   "r"((b)[0]), "r"((b)[1]))

// bf16 hi/lo split: x ~= hi + lo with ~16-bit combined mantissa
__device__ __forceinline__ void split_bf16(float f, ushort& h, ushort& l) {
    __nv_bfloat16 bh = __float2bfloat16_rn(f);
    float rh = __bfloat162float(bh);
    __nv_bfloat16 bl = __float2bfloat16_rn(f - rh);
    h = *(ushort*)&bh;
    l = *(ushort*)&bl;
}

// ===========================================================================
// GEMM (HMMA bf16x3): Y[n,128] = (RELU ? relu(X) : X) @ W[128,128]
// CTA: 128x128 tile, 8 warps (4m x 2n), warp tile 32x64.
// smem: Xhi/Xlo [128][136] bf16 (row-major, m x k),
//       Whi/Wlo [128][136] bf16 (row-major, k x n; B via ldmatrix.trans).
// D = Ah*Bh + Ah*Bl + Al*Bh, fp32 accum (lo*lo dropped, O(2^-18)).
// ===========================================================================
#define LDS_ 136                      // padded row length (bf16 elems)
#define OFF_XH 0
#define OFF_XL (OFF_XH + 128 * LDS_ * 2)
#define OFF_WH (OFF_XL + 128 * LDS_ * 2)
#define OFF_WL (OFF_WH + 128 * LDS_ * 2)
#define GEMM_SMEM_BYTES (OFF_WL + 128 * LDS_ * 2)

template <int RELU>
__global__ __launch_bounds__(256, 1) void gemm_mma_kernel(
    const float* __restrict__ X, const float* __restrict__ W,
    float* __restrict__ Y, int n)
{
    extern __shared__ char sm[];
    const int t   = threadIdx.x;
    const int lid = t & 31;
    const int wid = t >> 5;
    const int row0 = blockIdx.x * 128;

    // ---- Stage X tile split hi/lo (coalesced float4 reads)
    for (int i = t; i < 128 * 32; i += 256) {
        int m = i >> 5, q = i & 31;
        int r = row0 + m;
        int rc = r < n ? r : 0;
        float4 v = __ldg((const float4*)(X + (size_t)rc * HID) + q);
        if (RELU) {
            v.x = fmaxf(v.x, 0.f); v.y = fmaxf(v.y, 0.f);
            v.z = fmaxf(v.z, 0.f); v.w = fmaxf(v.w, 0.f);
        }
        float f[4] = {v.x, v.y, v.z, v.w};
        ushort h[4], l[4];
#pragma unroll
        for (int j = 0; j < 4; j++) split_bf16(f[j], h[j], l[j]);
        uint2 hp = make_uint2((uint32_t)h[0] | ((uint32_t)h[1] << 16),
                              (uint32_t)h[2] | ((uint32_t)h[3] << 16));
        uint2 lp = make_uint2((uint32_t)l[0] | ((uint32_t)l[1] << 16),
                              (uint32_t)l[2] | ((uint32_t)l[3] << 16));
        size_t off = ((size_t)m * LDS_ + q * 4) * 2;
        *(uint2*)(sm + OFF_XH + off) = hp;
        *(uint2*)(sm + OFF_XL + off) = lp;
    }

    // ---- Stage W split hi/lo, row-major [k][n] (no transpose)
    for (int i = t; i < 128 * 32; i += 256) {
        int k = i >> 5, q = i & 31;
        float4 v = __ldg((const float4*)(W + (size_t)k * HID) + q);
        float f[4] = {v.x, v.y, v.z, v.w};
        ushort h[4], l[4];
#pragma unroll
        for (int j = 0; j < 4; j++) split_bf16(f[j], h[j], l[j]);
        uint2 hp = make_uint2((uint32_t)h[0] | ((uint32_t)h[1] << 16),
                              (uint32_t)h[2] | ((uint32_t)h[3] << 16));
        uint2 lp = make_uint2((uint32_t)l[0] | ((uint32_t)l[1] << 16),
                              (uint32_t)l[2] | ((uint32_t)l[3] << 16));
        size_t off = ((size_t)k * LDS_ + q * 4) * 2;
        *(uint2*)(sm + OFF_WH + off) = hp;
        *(uint2*)(sm + OFF_WL + off) = lp;
    }
    __syncthreads();

    const int wm = wid & 3;          // 0..3 -> 32-row band
    const int wn = wid >> 2;         // 0..1 -> 64-col band

    // ldmatrix per-lane addressing: mat = lid>>3
    const int mat = lid >> 3;
    const int rsel = (mat & 1) * 8 + (lid & 7);   // row within 16
    const int csel = (mat >> 1) * 8;              // col offset 0/8

    const uint32_t sb = smem_u32(sm);
    // A: rows wm*32 + mi*16 + rsel, cols k + csel
    uint32_t aH = sb + OFF_XH + (uint32_t)(((wm * 32 + rsel) * LDS_ + csel) * 2);
    uint32_t aL = aH + (OFF_XL - OFF_XH);
    // B: k-rows rsel (+ks*16), cols wn*64 + nj*16 + csel
    uint32_t bH = sb + OFF_WH + (uint32_t)((rsel * LDS_ + wn * 64 + csel) * 2);
    uint32_t bL = bH + (OFF_WL - OFF_WH);

    float acc[2][8][4];
#pragma unroll
    for (int mi = 0; mi < 2; mi++)
#pragma unroll
        for (int nj = 0; nj < 8; nj++)
#pragma unroll
            for (int e = 0; e < 4; e++) acc[mi][nj][e] = 0.f;

#pragma unroll
    for (int ks = 0; ks < 8; ks++) {
        const uint32_t ao = ks * 32;                 // +16 halves in k
        const uint32_t bo = (uint32_t)(ks * 16 * LDS_ * 2);  // +16 k-rows

        uint32_t ah[2][4], al[2][4];
        LDM_X4(ah[0][0], ah[0][1], ah[0][2], ah[0][3], aH + ao);
        LDM_X4(ah[1][0], ah[1][1], ah[1][2], ah[1][3], aH + ao + 16 * LDS_ * 2);
        LDM_X4(al[0][0], al[0][1], al[0][2], al[0][3], aL + ao);
        LDM_X4(al[1][0], al[1][1], al[1][2], al[1][3], aL + ao + 16 * LDS_ * 2);

        uint32_t bh[8][2], bl[8][2];
#pragma unroll
        for (int g = 0; g < 4; g++) {
            LDM_X4T(bh[g * 2][0], bh[g * 2][1], bh[g * 2 + 1][0], bh[g * 2 + 1][1],
                    bH + bo + g * 32);
            LDM_X4T(bl[g * 2][0], bl[g * 2][1], bl[g * 2 + 1][0], bl[g * 2 + 1][1],
                    bL + bo + g * 32);
        }

#pragma unroll
        for (int mi = 0; mi < 2; mi++)
#pragma unroll
            for (int nj = 0; nj < 8; nj++) {
                MMA_BF16(acc[mi][nj], ah[mi], bh[nj]);
                MMA_BF16(acc[mi][nj], ah[mi], bl[nj]);
                MMA_BF16(acc[mi][nj], al[mi], bh[nj]);
            }
    }

    // ---- Epilogue: m16n8 f32 frag: d0,d1 at (g, 2c),(g, 2c+1); d2,d3 at (+8)
    const int g  = lid >> 2;
    const int c2 = (lid & 3) * 2;
#pragma unroll
    for (int mi = 0; mi < 2; mi++) {
        int rbase = row0 + wm * 32 + mi * 16;
        int r1 = rbase + g, r2 = rbase + g + 8;
#pragma unroll
        for (int nj = 0; nj < 8; nj++) {
            int col = wn * 64 + nj * 8 + c2;
            if (r1 < n)
                *(float2*)(Y + (size_t)r1 * HID + col) =
                    make_float2(acc[mi][nj][0], acc[mi][nj][1]);
            if (r2 < n)
                *(float2*)(Y + (size_t)r2 * HID + col) =
                    make_float2(acc[mi][nj][2], acc[mi][nj][3]);
        }
    }
}

// ---------------------------------------------------------------------------
// Scatter: out[dst] += w_e * F[src]. One warp per 4 edges (MLP=4),
// red.global.add.v4.f32 (REDG, no return trip). (L2-throughput bound.)
// ---------------------------------------------------------------------------
__global__ __launch_bounds__(256) void scatter_kernel(
    const float* __restrict__ F, const int* __restrict__ ei,
    const float* __restrict__ ew, float* __restrict__ out, int E)
{
    int warp = (int)(((long long)blockIdx.x * blockDim.x + threadIdx.x) >> 5);
    int lane = threadIdx.x & 31;
    int e0 = warp * 4;
    if (e0 >= E) return;

    if (e0 + 4 <= E) {
        int4   s4 = __ldg((const int4*)ei + (e0 >> 2));
        int4   d4 = __ldg((const int4*)(ei + E) + (e0 >> 2));
        float4 w4 = __ldg((const float4*)ew + (e0 >> 2));

        float4 v0 = __ldg((const float4*)(F + (size_t)s4.x * HID) + lane);
        float4 v1 = __ldg((const float4*)(F + (size_t)s4.y * HID) + lane);
        float4 v2 = __ldg((const float4*)(F + (size_t)s4.z * HID) + lane);
        float4 v3 = __ldg((const float4*)(F + (size_t)s4.w * HID) + lane);

        v0.x *= w4.x; v0.y *= w4.x; v0.z *= w4.x; v0.w *= w4.x;
        v1.x *= w4.y; v1.y *= w4.y; v1.z *= w4.y; v1.w *= w4.y;
        v2.x *= w4.z; v2.y *= w4.z; v2.z *= w4.z; v2.w *= w4.z;
        v3.x *= w4.w; v3.y *= w4.w; v3.z *= w4.w; v3.w *= w4.w;

        float* p0 = out + (size_t)d4.x * HID + lane * 4;
        float* p1 = out + (size_t)d4.y * HID + lane * 4;
        float* p2 = out + (size_t)d4.z * HID + lane * 4;
        float* p3 = out + (size_t)d4.w * HID + lane * 4;
        asm volatile("red.global.add.v4.f32 [%0], {%1,%2,%3,%4};"
                     :: "l"(p0), "f"(v0.x), "f"(v0.y), "f"(v0.z), "f"(v0.w) : "memory");
        asm volatile("red.global.add.v4.f32 [%0], {%1,%2,%3,%4};"
                     :: "l"(p1), "f"(v1.x), "f"(v1.y), "f"(v1.z), "f"(v1.w) : "memory");
        asm volatile("red.global.add.v4.f32 [%0], {%1,%2,%3,%4};"
                     :: "l"(p2), "f"(v2.x), "f"(v2.y), "f"(v2.z), "f"(v2.w) : "memory");
        asm volatile("red.global.add.v4.f32 [%0], {%1,%2,%3,%4};"
                     :: "l"(p3), "f"(v3.x), "f"(v3.y), "f"(v3.z), "f"(v3.w) : "memory");
    } else {
        for (int e = e0; e < E; e++) {
            int   s = __ldg(ei + e);
            int   d = __ldg(ei + E + e);
            float w = __ldg(ew + e);
            float4 v = __ldg((const float4*)(F + (size_t)s * HID) + lane);
            v.x *= w; v.y *= w; v.z *= w; v.w *= w;
            float* p = out + (size_t)d * HID + lane * 4;
            asm volatile("red.global.add.v4.f32 [%0], {%1,%2,%3,%4};"
                         :: "l"(p), "f"(v.x), "f"(v.y), "f"(v.z), "f"(v.w) : "memory");
        }
    }
}

// ---------------------------------------------------------------------------
// Pair epilogue: out[p,:] = Wlin @ concat(z[a], z[b]); one warp per pair.
// ---------------------------------------------------------------------------
__global__ __launch_bounds__(256) void pair_kernel(
    const float* __restrict__ Z, const int* __restrict__ pe,
    const float* __restrict__ Wlin, float* __restrict__ out, int P)
{
    __shared__ float4 wl[128];   // Wlin [2][256] = 128 float4
    for (int i = threadIdx.x; i < 128; i += 256)
        wl[i] = __ldg((const float4*)Wlin + i);
    __syncthreads();

    long long t = (long long)blockIdx.x * blockDim.x + threadIdx.x;
    int p = (int)(t >> 5);
    if (p >= P) return;
    int lane = (int)(t & 31);

    int a = __ldg(pe + p);
    int b = __ldg(pe + P + p);

    float4 za = __ldg((const float4*)(Z + (size_t)a * HID) + lane);
    float4 zb = __ldg((const float4*)(Z + (size_t)b * HID) + lane);

    float4 w0a = wl[lane];
    float4 w0b = wl[32 + lane];
    float4 w1a = wl[64 + lane];
    float4 w1b = wl[96 + lane];

    float acc0 = za.x * w0a.x + za.y * w0a.y + za.z * w0a.z + za.w * w0a.w
               + zb.x * w0b.x + zb.y * w0b.y + zb.z * w0b.z + zb.w * w0b.w;
    float acc1 = za.x * w1a.x + za.y * w1a.y + za.z * w1a.z + za.w * w1a.w
               + zb.x * w1b.x + zb.y * w1b.y + zb.z * w1b.z + zb.w * w1b.w;

#pragma unroll
    for (int o = 16; o > 0; o >>= 1) {
        acc0 += __shfl_xor_sync(0xFFFFFFFFu, acc0, o);
        acc1 += __shfl_xor_sync(0xFFFFFFFFu, acc1, o);
    }
    if (lane == 0) {
        out[(size_t)p * 2]     = acc0;
        out[(size_t)p * 2 + 1] = acc1;
    }
}

// ---------------------------------------------------------------------------
// Launch
// Inputs: 0:x 1:edge_index1 2:edge_index2 3:edge_weight1 4:edge_weight2
//         5:pos_edge_index 6:W1 7:W2 8:Wlin      out: [P,2] float
// ---------------------------------------------------------------------------
extern "C" void kernel_launch(void* const* d_in, const int* in_sizes, int n_in,
                              void* d_out, int out_size)
{
    const float* x    = (const float*)d_in[0];
    const int*   ei1  = (const int*)  d_in[1];
    const int*   ei2  = (const int*)  d_in[2];
    const float* ew1  = (const float*)d_in[3];
    const float* ew2  = (const float*)d_in[4];
    const int*   pe   = (const int*)  d_in[5];
    const float* W1   = (const float*)d_in[6];
    const float* W2   = (const float*)d_in[7];
    const float* Wlin = (const float*)d_in[8];
    float* out = (float*)d_out;

    int n  = in_sizes[0] / HID;
    int E1 = in_sizes[3];
    int E2 = in_sizes[4];
    int P  = in_sizes[5] / 2;

    void *p_buf0, *p_h, *p_z;
    cudaGetSymbolAddress(&p_buf0, g_buf0);
    cudaGetSymbolAddress(&p_h,    g_h);
    cudaGetSymbolAddress(&p_z,    g_z);
    float* buf0 = (float*)p_buf0;
    float* h    = (float*)p_h;
    float* z    = (float*)p_z;

    cudaFuncSetAttribute(gemm_mma_kernel<0>,
        cudaFuncAttributeMaxDynamicSharedMemorySize, GEMM_SMEM_BYTES);
    cudaFuncSetAttribute(gemm_mma_kernel<1>,
        cudaFuncAttributeMaxDynamicSharedMemorySize, GEMM_SMEM_BYTES);

    size_t featBytes = (size_t)n * HID * sizeof(float);
    cudaMemsetAsync(h, 0, featBytes);
    cudaMemsetAsync(z, 0, featBytes);

    int gemmBlocks = (n + 127) / 128;

    // Layer 1: xw1 = x @ W1 ; h = scatter-add
    gemm_mma_kernel<0><<<gemmBlocks, 256, GEMM_SMEM_BYTES>>>(x, W1, buf0, n);
    {
        int warps = (E1 + 3) / 4;
        int blocks = (warps * 32 + 255) / 256;
        scatter_kernel<<<blocks, 256>>>(buf0, ei1, ew1, h, E1);
    }

    // Layer 2: hw2 = relu(h) @ W2 ; z = scatter-add
    gemm_mma_kernel<1><<<gemmBlocks, 256, GEMM_SMEM_BYTES>>>(h, W2, buf0, n);
    {
        int warps = (E2 + 3) / 4;
        int blocks = (warps * 32 + 255) / 256;
        scatter_kernel<<<blocks, 256>>>(buf0, ei2, ew2, z, E2);
    }

    // Pair epilogue
    {
        int warps = P;
        int blocks = (warps * 32 + 255) / 256;
        pair_kernel<<<blocks, 256>>>(z, pe, Wlin, out, P);
    }
}

// round 6
// speedup vs baseline: 1.6469x; 1.3018x over previous
#include <cuda_runtime.h>
#include <cuda_bf16.h>
#include <cstdint>

#define HID 128
#define NMAX 100000

__device__ float g_buf0[(size_t)NMAX * HID];  // xw1, then hw2
__device__ float g_h   [(size_t)NMAX * HID];  // layer-1 aggregate
__device__ float g_z   [(size_t)NMAX * HID];  // layer-2 aggregate

__device__ __forceinline__ uint32_t smem_u32(const void* p) {
    uint32_t a;
    asm("{ .reg .u64 t; cvta.to.shared.u64 t, %1; cvt.u32.u64 %0, t; }"
        : "=r"(a) : "l"(p));
    return a;
}

#define LDM_X4(r0, r1, r2, r3, a)                                             \
    asm volatile("ldmatrix.sync.aligned.m8n8.x4.shared.b16 {%0,%1,%2,%3}, [%4];" \
                 : "=r"(r0), "=r"(r1), "=r"(r2), "=r"(r3) : "r"(a))
#define LDM_X4T(r0, r1, r2, r3, a)                                            \
    asm volatile("ldmatrix.sync.aligned.m8n8.x4.trans.shared.b16 {%0,%1,%2,%3}, [%4];" \
                 : "=r"(r0), "=r"(r1), "=r"(r2), "=r"(r3) : "r"(a))
#define MMA_BF16(d, a, b)                                                     \
    asm volatile("mma.sync.aligned.m16n8k16.row.col.f32.bf16.bf16.f32 "       \
                 "{%0,%1,%2,%3}, {%4,%5,%6,%7}, {%8,%9}, {%0,%1,%2,%3};"      \
                 : "+f"((d)[0]), "+f"((d)[1]), "+f"((d)[2]), "+f"((d)[3])     \
                 : "r"((a)[0]), "r"((a)[1]), "r"((a)[2]), "r"((a)[3]),        \
                   "r"((b)[0]), "r"((b)[1]))

// Cheap hi/lo split: hi = truncate-to-bf16 (exact prefix), lo = rn(f - hi).
// Dropped lo*lo term => final rel err ~2^-16 per product, fine vs 1e-3.
__device__ __forceinline__ void split2(float f, ushort& h, ushort& l) {
    uint32_t fb = __float_as_uint(f);
    h = (ushort)(fb >> 16);
    float lo = f - __uint_as_float(fb & 0xFFFF0000u);   // exact
    __nv_bfloat16 bl = __float2bfloat16_rn(lo);
    l = *(ushort*)&bl;
}

// ===========================================================================
// GEMM (HMMA bf16x3): Y[n,128] = (RELU ? relu(X) : X) @ W[128,128]
// CTA: 64x128 tile, 8 warps (2m x 4n), warp tile 32x32. 2 CTAs/SM.
// Epilogue also zeroes Zero[row0..row0+63] (replaces memset of h / z).
// ===========================================================================
#define LDS_ 136
#define OFF_XH 0
#define OFF_XL (64 * LDS_ * 2)
#define OFF_WH (2 * 64 * LDS_ * 2)
#define OFF_WL (OFF_WH + 128 * LDS_ * 2)
#define GEMM_SMEM_BYTES (OFF_WL + 128 * LDS_ * 2)   // 104,448 B

template <int RELU>
__global__ __launch_bounds__(256, 2) void gemm_mma_kernel(
    const float* __restrict__ X, const float* __restrict__ W,
    float* __restrict__ Y, float* __restrict__ Zero, int n)
{
    extern __shared__ char sm[];
    const int t   = threadIdx.x;
    const int lid = t & 31;
    const int wid = t >> 5;
    const int row0 = blockIdx.x * 64;

    // ---- Zero pass (replaces cudaMemset of the aggregate buffer)
    {
        float4 z4 = make_float4(0.f, 0.f, 0.f, 0.f);
        for (int i = t; i < 64 * 32; i += 256) {
            int m = i >> 5, q = i & 31;
            int r = row0 + m;
            if (r < n) ((float4*)(Zero + (size_t)r * HID))[q] = z4;
        }
    }

    // ---- Stage X tile split hi/lo
    for (int i = t; i < 64 * 32; i += 256) {
        int m = i >> 5, q = i & 31;
        int r = row0 + m;
        int rc = r < n ? r : 0;
        float4 v = __ldg((const float4*)(X + (size_t)rc * HID) + q);
        if (RELU) {
            v.x = fmaxf(v.x, 0.f); v.y = fmaxf(v.y, 0.f);
            v.z = fmaxf(v.z, 0.f); v.w = fmaxf(v.w, 0.f);
        }
        float f[4] = {v.x, v.y, v.z, v.w};
        ushort h[4], l[4];
#pragma unroll
        for (int j = 0; j < 4; j++) split2(f[j], h[j], l[j]);
        uint2 hp = make_uint2((uint32_t)h[0] | ((uint32_t)h[1] << 16),
                              (uint32_t)h[2] | ((uint32_t)h[3] << 16));
        uint2 lp = make_uint2((uint32_t)l[0] | ((uint32_t)l[1] << 16),
                              (uint32_t)l[2] | ((uint32_t)l[3] << 16));
        size_t off = ((size_t)m * LDS_ + q * 4) * 2;
        *(uint2*)(sm + OFF_XH + off) = hp;
        *(uint2*)(sm + OFF_XL + off) = lp;
    }

    // ---- Stage W split hi/lo, row-major [k][n]
    for (int i = t; i < 128 * 32; i += 256) {
        int k = i >> 5, q = i & 31;
        float4 v = __ldg((const float4*)(W + (size_t)k * HID) + q);
        float f[4] = {v.x, v.y, v.z, v.w};
        ushort h[4], l[4];
#pragma unroll
        for (int j = 0; j < 4; j++) split2(f[j], h[j], l[j]);
        uint2 hp = make_uint2((uint32_t)h[0] | ((uint32_t)h[1] << 16),
                              (uint32_t)h[2] | ((uint32_t)h[3] << 16));
        uint2 lp = make_uint2((uint32_t)l[0] | ((uint32_t)l[1] << 16),
                              (uint32_t)l[2] | ((uint32_t)l[3] << 16));
        size_t off = ((size_t)k * LDS_ + q * 4) * 2;
        *(uint2*)(sm + OFF_WH + off) = hp;
        *(uint2*)(sm + OFF_WL + off) = lp;
    }
    __syncthreads();

    const int wm = wid & 1;          // 0..1 -> 32-row band
    const int wn = wid >> 1;         // 0..3 -> 32-col band

    const int mat  = lid >> 3;
    const int rsel = (mat & 1) * 8 + (lid & 7);
    const int csel = (mat >> 1) * 8;

    const uint32_t sb = smem_u32(sm);
    uint32_t aH = sb + OFF_XH + (uint32_t)(((wm * 32 + rsel) * LDS_ + csel) * 2);
    uint32_t aL = aH + (OFF_XL - OFF_XH);
    uint32_t bH = sb + OFF_WH + (uint32_t)((rsel * LDS_ + wn * 32 + csel) * 2);
    uint32_t bL = bH + (OFF_WL - OFF_WH);

    float acc[2][4][4];
#pragma unroll
    for (int mi = 0; mi < 2; mi++)
#pragma unroll
        for (int nj = 0; nj < 4; nj++)
#pragma unroll
            for (int e = 0; e < 4; e++) acc[mi][nj][e] = 0.f;

#pragma unroll
    for (int ks = 0; ks < 8; ks++) {
        const uint32_t ao = ks * 32;                       // +16 k elems
        const uint32_t bo = (uint32_t)(ks * 16 * LDS_ * 2);

        uint32_t ah[2][4], al[2][4];
        LDM_X4(ah[0][0], ah[0][1], ah[0][2], ah[0][3], aH + ao);
        LDM_X4(ah[1][0], ah[1][1], ah[1][2], ah[1][3], aH + ao + 16 * LDS_ * 2);
        LDM_X4(al[0][0], al[0][1], al[0][2], al[0][3], aL + ao);
        LDM_X4(al[1][0], al[1][1], al[1][2], al[1][3], aL + ao + 16 * LDS_ * 2);

        uint32_t bh[4][2], bl[4][2];
#pragma unroll
        for (int g = 0; g < 2; g++) {
            LDM_X4T(bh[g * 2][0], bh[g * 2][1], bh[g * 2 + 1][0], bh[g * 2 + 1][1],
                    bH + bo + g * 32);
            LDM_X4T(bl[g * 2][0], bl[g * 2][1], bl[g * 2 + 1][0], bl[g * 2 + 1][1],
                    bL + bo + g * 32);
        }

#pragma unroll
        for (int mi = 0; mi < 2; mi++)
#pragma unroll
            for (int nj = 0; nj < 4; nj++) {
                MMA_BF16(acc[mi][nj], ah[mi], bh[nj]);
                MMA_BF16(acc[mi][nj], ah[mi], bl[nj]);
                MMA_BF16(acc[mi][nj], al[mi], bh[nj]);
            }
    }

    const int g  = lid >> 2;
    const int c2 = (lid & 3) * 2;
#pragma unroll
    for (int mi = 0; mi < 2; mi++) {
        int rbase = row0 + wm * 32 + mi * 16;
        int r1 = rbase + g, r2 = rbase + g + 8;
#pragma unroll
        for (int nj = 0; nj < 4; nj++) {
            int col = wn * 32 + nj * 8 + c2;
            if (r1 < n)
                *(float2*)(Y + (size_t)r1 * HID + col) =
                    make_float2(acc[mi][nj][0], acc[mi][nj][1]);
            if (r2 < n)
                *(float2*)(Y + (size_t)r2 * HID + col) =
                    make_float2(acc[mi][nj][2], acc[mi][nj][3]);
        }
    }
}

// ---------------------------------------------------------------------------
// Scatter: out[dst] += w_e * F[src]. One warp per 8 edges (MLP=8),
// red.global.add.v4.f32 (REDG, no return trip).
// ---------------------------------------------------------------------------
__global__ __launch_bounds__(256) void scatter_kernel(
    const float* __restrict__ F, const int* __restrict__ ei,
    const float* __restrict__ ew, float* __restrict__ out, int E)
{
    int warp = (int)(((long long)blockIdx.x * blockDim.x + threadIdx.x) >> 5);
    int lane = threadIdx.x & 31;
    int e0 = warp * 8;
    if (e0 >= E) return;

    if (e0 + 8 <= E) {
        int q = e0 >> 2;
        int4   sa = __ldg((const int4*)ei + q);
        int4   sb = __ldg((const int4*)ei + q + 1);
        int4   da = __ldg((const int4*)(ei + E) + q);
        int4   db = __ldg((const int4*)(ei + E) + q + 1);
        float4 wa = __ldg((const float4*)ew + q);
        float4 wb = __ldg((const float4*)ew + q + 1);

        int   s[8] = {sa.x, sa.y, sa.z, sa.w, sb.x, sb.y, sb.z, sb.w};
        int   d[8] = {da.x, da.y, da.z, da.w, db.x, db.y, db.z, db.w};
        float w[8] = {wa.x, wa.y, wa.z, wa.w, wb.x, wb.y, wb.z, wb.w};

        float4 v[8];
#pragma unroll
        for (int j = 0; j < 8; j++)
            v[j] = __ldg((const float4*)(F + (size_t)s[j] * HID) + lane);
#pragma unroll
        for (int j = 0; j < 8; j++) {
            v[j].x *= w[j]; v[j].y *= w[j]; v[j].z *= w[j]; v[j].w *= w[j];
            float* p = out + (size_t)d[j] * HID + lane * 4;
            asm volatile("red.global.add.v4.f32 [%0], {%1,%2,%3,%4};"
                         :: "l"(p), "f"(v[j].x), "f"(v[j].y), "f"(v[j].z), "f"(v[j].w)
                         : "memory");
        }
    } else {
        for (int e = e0; e < E; e++) {
            int   s = __ldg(ei + e);
            int   d = __ldg(ei + E + e);
            float w = __ldg(ew + e);
            float4 v = __ldg((const float4*)(F + (size_t)s * HID) + lane);
            v.x *= w; v.y *= w; v.z *= w; v.w *= w;
            float* p = out + (size_t)d * HID + lane * 4;
            asm volatile("red.global.add.v4.f32 [%0], {%1,%2,%3,%4};"
                         :: "l"(p), "f"(v.x), "f"(v.y), "f"(v.z), "f"(v.w) : "memory");
        }
    }
}

// ---------------------------------------------------------------------------
// Pair epilogue: out[p,:] = Wlin @ concat(z[a], z[b]); one warp per 4 pairs.
// ---------------------------------------------------------------------------
__global__ __launch_bounds__(256) void pair_kernel(
    const float* __restrict__ Z, const int* __restrict__ pe,
    const float* __restrict__ Wlin, float* __restrict__ out, int P)
{
    __shared__ float4 wl[128];   // Wlin [2][256] = 128 float4
    for (int i = threadIdx.x; i < 128; i += 256)
        wl[i] = __ldg((const float4*)Wlin + i);
    __syncthreads();

    int warp = (int)(((long long)blockIdx.x * blockDim.x + threadIdx.x) >> 5);
    int lane = threadIdx.x & 31;
    int p0 = warp * 4;
    if (p0 >= P) return;

    float4 w0a = wl[lane];
    float4 w0b = wl[32 + lane];
    float4 w1a = wl[64 + lane];
    float4 w1b = wl[96 + lane];

    if (p0 + 4 <= P) {
        int4 pa = __ldg((const int4*)pe + (p0 >> 2));
        int4 pb = __ldg((const int4*)(pe + P) + (p0 >> 2));
        int a[4] = {pa.x, pa.y, pa.z, pa.w};
        int b[4] = {pb.x, pb.y, pb.z, pb.w};

        float4 za[4], zb[4];
#pragma unroll
        for (int j = 0; j < 4; j++) {
            za[j] = __ldg((const float4*)(Z + (size_t)a[j] * HID) + lane);
            zb[j] = __ldg((const float4*)(Z + (size_t)b[j] * HID) + lane);
        }

        float r[8];
#pragma unroll
        for (int j = 0; j < 4; j++) {
            float acc0 = za[j].x*w0a.x + za[j].y*w0a.y + za[j].z*w0a.z + za[j].w*w0a.w
                       + zb[j].x*w0b.x + zb[j].y*w0b.y + zb[j].z*w0b.z + zb[j].w*w0b.w;
            float acc1 = za[j].x*w1a.x + za[j].y*w1a.y + za[j].z*w1a.z + za[j].w*w1a.w
                       + zb[j].x*w1b.x + zb[j].y*w1b.y + zb[j].z*w1b.z + zb[j].w*w1b.w;
#pragma unroll
            for (int o = 16; o > 0; o >>= 1) {
                acc0 += __shfl_xor_sync(0xFFFFFFFFu, acc0, o);
                acc1 += __shfl_xor_sync(0xFFFFFFFFu, acc1, o);
            }
            r[j * 2] = acc0; r[j * 2 + 1] = acc1;
        }
        if (lane == 0) {
            float4* op = (float4*)(out + (size_t)p0 * 2);
            op[0] = make_float4(r[0], r[1], r[2], r[3]);
            op[1] = make_float4(r[4], r[5], r[6], r[7]);
        }
    } else {
        for (int p = p0; p < P; p++) {
            int a = __ldg(pe + p);
            int b = __ldg(pe + P + p);
            float4 za = __ldg((const float4*)(Z + (size_t)a * HID) + lane);
            float4 zb = __ldg((const float4*)(Z + (size_t)b * HID) + lane);
            float acc0 = za.x*w0a.x + za.y*w0a.y + za.z*w0a.z + za.w*w0a.w
                       + zb.x*w0b.x + zb.y*w0b.y + zb.z*w0b.z + zb.w*w0b.w;
            float acc1 = za.x*w1a.x + za.y*w1a.y + za.z*w1a.z + za.w*w1a.w
                       + zb.x*w1b.x + zb.y*w1b.y + zb.z*w1b.z + zb.w*w1b.w;
#pragma unroll
            for (int o = 16; o > 0; o >>= 1) {
                acc0 += __shfl_xor_sync(0xFFFFFFFFu, acc0, o);
                acc1 += __shfl_xor_sync(0xFFFFFFFFu, acc1, o);
            }
            if (lane == 0) {
                out[(size_t)p * 2]     = acc0;
                out[(size_t)p * 2 + 1] = acc1;
            }
        }
    }
}

// ---------------------------------------------------------------------------
// Launch
// ---------------------------------------------------------------------------
extern "C" void kernel_launch(void* const* d_in, const int* in_sizes, int n_in,
                              void* d_out, int out_size)
{
    const float* x    = (const float*)d_in[0];
    const int*   ei1  = (const int*)  d_in[1];
    const int*   ei2  = (const int*)  d_in[2];
    const float* ew1  = (const float*)d_in[3];
    const float* ew2  = (const float*)d_in[4];
    const int*   pe   = (const int*)  d_in[5];
    const float* W1   = (const float*)d_in[6];
    const float* W2   = (const float*)d_in[7];
    const float* Wlin = (const float*)d_in[8];
    float* out = (float*)d_out;

    int n  = in_sizes[0] / HID;
    int E1 = in_sizes[3];
    int E2 = in_sizes[4];
    int P  = in_sizes[5] / 2;

    void *p_buf0, *p_h, *p_z;
    cudaGetSymbolAddress(&p_buf0, g_buf0);
    cudaGetSymbolAddress(&p_h,    g_h);
    cudaGetSymbolAddress(&p_z,    g_z);
    float* buf0 = (float*)p_buf0;
    float* h    = (float*)p_h;
    float* z    = (float*)p_z;

    cudaFuncSetAttribute(gemm_mma_kernel<0>,
        cudaFuncAttributeMaxDynamicSharedMemorySize, GEMM_SMEM_BYTES);
    cudaFuncSetAttribute(gemm_mma_kernel<1>,
        cudaFuncAttributeMaxDynamicSharedMemorySize, GEMM_SMEM_BYTES);

    int gemmBlocks = (n + 63) / 64;

    // Layer 1: buf0 = x @ W1 (also zeroes h) ; h = scatter-add
    gemm_mma_kernel<0><<<gemmBlocks, 256, GEMM_SMEM_BYTES>>>(x, W1, buf0, h, n);
    {
        int warps = (E1 + 7) / 8;
        int blocks = (warps * 32 + 255) / 256;
        scatter_kernel<<<blocks, 256>>>(buf0, ei1, ew1, h, E1);
    }

    // Layer 2: buf0 = relu(h) @ W2 (also zeroes z) ; z = scatter-add
    gemm_mma_kernel<1><<<gemmBlocks, 256, GEMM_SMEM_BYTES>>>(h, W2, buf0, z, n);
    {
        int warps = (E2 + 7) / 8;
        int blocks = (warps * 32 + 255) / 256;
        scatter_kernel<<<blocks, 256>>>(buf0, ei2, ew2, z, E2);
    }

    // Pair epilogue
    {
        int warps = (P + 3) / 4;
        int blocks = (warps * 32 + 255) / 256;
        pair_kernel<<<blocks, 256>>>(z, pe, Wlin, out, P);
    }
}

// round 7
// speedup vs baseline: 2.6119x; 1.5859x over previous
#include <cuda_runtime.h>
#include <cuda_bf16.h>
#include <cstdint>

#define HID 128
#define NMAX 100000

__device__ float g_buf0[(size_t)NMAX * HID];  // xw1
__device__ float g_h   [(size_t)NMAX * HID];  // layer-1 aggregate
__device__ float g_y2  [(size_t)NMAX * 4];    // relu(h) @ V
__device__ float g_c   [(size_t)NMAX * 4];    // layer-2 collapsed aggregate
__device__ float g_V   [HID * 4];             // W2 @ WlinPacked

__device__ __forceinline__ uint32_t smem_u32(const void* p) {
    uint32_t a;
    asm("{ .reg .u64 t; cvta.to.shared.u64 t, %1; cvt.u32.u64 %0, t; }"
        : "=r"(a) : "l"(p));
    return a;
}

#define LDM_X4(r0, r1, r2, r3, a)                                             \
    asm volatile("ldmatrix.sync.aligned.m8n8.x4.shared.b16 {%0,%1,%2,%3}, [%4];" \
                 : "=r"(r0), "=r"(r1), "=r"(r2), "=r"(r3) : "r"(a))
#define LDM_X4T(r0, r1, r2, r3, a)                                            \
    asm volatile("ldmatrix.sync.aligned.m8n8.x4.trans.shared.b16 {%0,%1,%2,%3}, [%4];" \
                 : "=r"(r0), "=r"(r1), "=r"(r2), "=r"(r3) : "r"(a))
#define MMA_BF16(d, a, b)                                                     \
    asm volatile("mma.sync.aligned.m16n8k16.row.col.f32.bf16.bf16.f32 "       \
                 "{%0,%1,%2,%3}, {%4,%5,%6,%7}, {%8,%9}, {%0,%1,%2,%3};"      \
                 : "+f"((d)[0]), "+f"((d)[1]), "+f"((d)[2]), "+f"((d)[3])     \
                 : "r"((a)[0]), "r"((a)[1]), "r"((a)[2]), "r"((a)[3]),        \
                   "r"((b)[0]), "r"((b)[1]))

// Cheap hi/lo split: hi = truncate-to-bf16 (exact prefix), lo = rn(f - hi).
__device__ __forceinline__ void split2(float f, ushort& h, ushort& l) {
    uint32_t fb = __float_as_uint(f);
    h = (ushort)(fb >> 16);
    float lo = f - __uint_as_float(fb & 0xFFFF0000u);   // exact
    __nv_bfloat16 bl = __float2bfloat16_rn(lo);
    l = *(ushort*)&bl;
}

// ===========================================================================
// GEMM1 (HMMA bf16x3): Y[n,128] = X @ W[128,128]; also zeroes Zero rows.
// CTA: 64x128 tile, 8 warps (2m x 4n), warp tile 32x32. 2 CTAs/SM.
// ===========================================================================
#define LDS_ 136
#define OFF_XH 0
#define OFF_XL (64 * LDS_ * 2)
#define OFF_WH (2 * 64 * LDS_ * 2)
#define OFF_WL (OFF_WH + 128 * LDS_ * 2)
#define GEMM_SMEM_BYTES (OFF_WL + 128 * LDS_ * 2)   // 104,448 B

__global__ __launch_bounds__(256, 2) void gemm_mma_kernel(
    const float* __restrict__ X, const float* __restrict__ W,
    float* __restrict__ Y, float* __restrict__ Zero, int n)
{
    extern __shared__ char sm[];
    const int t   = threadIdx.x;
    const int lid = t & 31;
    const int wid = t >> 5;
    const int row0 = blockIdx.x * 64;

    // ---- Zero pass (replaces cudaMemset of the aggregate buffer)
    {
        float4 z4 = make_float4(0.f, 0.f, 0.f, 0.f);
        for (int i = t; i < 64 * 32; i += 256) {
            int m = i >> 5, q = i & 31;
            int r = row0 + m;
            if (r < n) ((float4*)(Zero + (size_t)r * HID))[q] = z4;
        }
    }

    // ---- Stage X tile split hi/lo
    for (int i = t; i < 64 * 32; i += 256) {
        int m = i >> 5, q = i & 31;
        int r = row0 + m;
        int rc = r < n ? r : 0;
        float4 v = __ldg((const float4*)(X + (size_t)rc * HID) + q);
        float f[4] = {v.x, v.y, v.z, v.w};
        ushort h[4], l[4];
#pragma unroll
        for (int j = 0; j < 4; j++) split2(f[j], h[j], l[j]);
        uint2 hp = make_uint2((uint32_t)h[0] | ((uint32_t)h[1] << 16),
                              (uint32_t)h[2] | ((uint32_t)h[3] << 16));
        uint2 lp = make_uint2((uint32_t)l[0] | ((uint32_t)l[1] << 16),
                              (uint32_t)l[2] | ((uint32_t)l[3] << 16));
        size_t off = ((size_t)m * LDS_ + q * 4) * 2;
        *(uint2*)(sm + OFF_XH + off) = hp;
        *(uint2*)(sm + OFF_XL + off) = lp;
    }

    // ---- Stage W split hi/lo, row-major [k][n]
    for (int i = t; i < 128 * 32; i += 256) {
        int k = i >> 5, q = i & 31;
        float4 v = __ldg((const float4*)(W + (size_t)k * HID) + q);
        float f[4] = {v.x, v.y, v.z, v.w};
        ushort h[4], l[4];
#pragma unroll
        for (int j = 0; j < 4; j++) split2(f[j], h[j], l[j]);
        uint2 hp = make_uint2((uint32_t)h[0] | ((uint32_t)h[1] << 16),
                              (uint32_t)h[2] | ((uint32_t)h[3] << 16));
        uint2 lp = make_uint2((uint32_t)l[0] | ((uint32_t)l[1] << 16),
                              (uint32_t)l[2] | ((uint32_t)l[3] << 16));
        size_t off = ((size_t)k * LDS_ + q * 4) * 2;
        *(uint2*)(sm + OFF_WH + off) = hp;
        *(uint2*)(sm + OFF_WL + off) = lp;
    }
    __syncthreads();

    const int wm = wid & 1;
    const int wn = wid >> 1;
    const int mat  = lid >> 3;
    const int rsel = (mat & 1) * 8 + (lid & 7);
    const int csel = (mat >> 1) * 8;

    const uint32_t sb = smem_u32(sm);
    uint32_t aH = sb + OFF_XH + (uint32_t)(((wm * 32 + rsel) * LDS_ + csel) * 2);
    uint32_t aL = aH + (OFF_XL - OFF_XH);
    uint32_t bH = sb + OFF_WH + (uint32_t)((rsel * LDS_ + wn * 32 + csel) * 2);
    uint32_t bL = bH + (OFF_WL - OFF_WH);

    float acc[2][4][4];
#pragma unroll
    for (int mi = 0; mi < 2; mi++)
#pragma unroll
        for (int nj = 0; nj < 4; nj++)
#pragma unroll
            for (int e = 0; e < 4; e++) acc[mi][nj][e] = 0.f;

#pragma unroll
    for (int ks = 0; ks < 8; ks++) {
        const uint32_t ao = ks * 32;
        const uint32_t bo = (uint32_t)(ks * 16 * LDS_ * 2);

        uint32_t ah[2][4], al[2][4];
        LDM_X4(ah[0][0], ah[0][1], ah[0][2], ah[0][3], aH + ao);
        LDM_X4(ah[1][0], ah[1][1], ah[1][2], ah[1][3], aH + ao + 16 * LDS_ * 2);
        LDM_X4(al[0][0], al[0][1], al[0][2], al[0][3], aL + ao);
        LDM_X4(al[1][0], al[1][1], al[1][2], al[1][3], aL + ao + 16 * LDS_ * 2);

        uint32_t bh[4][2], bl[4][2];
#pragma unroll
        for (int g = 0; g < 2; g++) {
            LDM_X4T(bh[g * 2][0], bh[g * 2][1], bh[g * 2 + 1][0], bh[g * 2 + 1][1],
                    bH + bo + g * 32);
            LDM_X4T(bl[g * 2][0], bl[g * 2][1], bl[g * 2 + 1][0], bl[g * 2 + 1][1],
                    bL + bo + g * 32);
        }

#pragma unroll
        for (int mi = 0; mi < 2; mi++)
#pragma unroll
            for (int nj = 0; nj < 4; nj++) {
                MMA_BF16(acc[mi][nj], ah[mi], bh[nj]);
                MMA_BF16(acc[mi][nj], ah[mi], bl[nj]);
                MMA_BF16(acc[mi][nj], al[mi], bh[nj]);
            }
    }

    const int g  = lid >> 2;
    const int c2 = (lid & 3) * 2;
#pragma unroll
    for (int mi = 0; mi < 2; mi++) {
        int rbase = row0 + wm * 32 + mi * 16;
        int r1 = rbase + g, r2 = rbase + g + 8;
#pragma unroll
        for (int nj = 0; nj < 4; nj++) {
            int col = wn * 32 + nj * 8 + c2;
            if (r1 < n)
                *(float2*)(Y + (size_t)r1 * HID + col) =
                    make_float2(acc[mi][nj][0], acc[mi][nj][1]);
            if (r2 < n)
                *(float2*)(Y + (size_t)r2 * HID + col) =
                    make_float2(acc[mi][nj][2], acc[mi][nj][3]);
        }
    }
}

// ---------------------------------------------------------------------------
// Scatter (wide, layer 1): out[dst] += w_e * F[src]. One warp per 8 edges.
// ---------------------------------------------------------------------------
__global__ __launch_bounds__(256) void scatter_kernel(
    const float* __restrict__ F, const int* __restrict__ ei,
    const float* __restrict__ ew, float* __restrict__ out, int E)
{
    int warp = (int)(((long long)blockIdx.x * blockDim.x + threadIdx.x) >> 5);
    int lane = threadIdx.x & 31;
    int e0 = warp * 8;
    if (e0 >= E) return;

    if (e0 + 8 <= E) {
        int q = e0 >> 2;
        int4   sa = __ldg((const int4*)ei + q);
        int4   sb = __ldg((const int4*)ei + q + 1);
        int4   da = __ldg((const int4*)(ei + E) + q);
        int4   db = __ldg((const int4*)(ei + E) + q + 1);
        float4 wa = __ldg((const float4*)ew + q);
        float4 wb = __ldg((const float4*)ew + q + 1);

        int   s[8] = {sa.x, sa.y, sa.z, sa.w, sb.x, sb.y, sb.z, sb.w};
        int   d[8] = {da.x, da.y, da.z, da.w, db.x, db.y, db.z, db.w};
        float w[8] = {wa.x, wa.y, wa.z, wa.w, wb.x, wb.y, wb.z, wb.w};

        float4 v[8];
#pragma unroll
        for (int j = 0; j < 8; j++)
            v[j] = __ldg((const float4*)(F + (size_t)s[j] * HID) + lane);
#pragma unroll
        for (int j = 0; j < 8; j++) {
            v[j].x *= w[j]; v[j].y *= w[j]; v[j].z *= w[j]; v[j].w *= w[j];
            float* p = out + (size_t)d[j] * HID + lane * 4;
            asm volatile("red.global.add.v4.f32 [%0], {%1,%2,%3,%4};"
                         :: "l"(p), "f"(v[j].x), "f"(v[j].y), "f"(v[j].z), "f"(v[j].w)
                         : "memory");
        }
    } else {
        for (int e = e0; e < E; e++) {
            int   s = __ldg(ei + e);
            int   d = __ldg(ei + E + e);
            float w = __ldg(ew + e);
            float4 v = __ldg((const float4*)(F + (size_t)s * HID) + lane);
            v.x *= w; v.y *= w; v.z *= w; v.w *= w;
            float* p = out + (size_t)d * HID + lane * 4;
            asm volatile("red.global.add.v4.f32 [%0], {%1,%2,%3,%4};"
                         :: "l"(p), "f"(v.x), "f"(v.y), "f"(v.z), "f"(v.w) : "memory");
        }
    }
}

// ---------------------------------------------------------------------------
// V = W2 @ WlinPacked: V[k][j] = sum_c W2[k,c] * wl_j[c]
// wl_0 = Wlin[0,0:128], wl_1 = Wlin[0,128:256], wl_2 = Wlin[1,0:128],
// wl_3 = Wlin[1,128:256].
// ---------------------------------------------------------------------------
__global__ void vpack_kernel(const float* __restrict__ W2,
                             const float* __restrict__ Wlin,
                             float* __restrict__ V)
{
    int i = threadIdx.x;          // 0..511
    int k = i >> 2, j = i & 3;
    const float* wl = Wlin + (j >> 1) * 256 + (j & 1) * 128;
    const float* wr = W2 + (size_t)k * HID;
    float acc = 0.f;
#pragma unroll 8
    for (int c = 0; c < HID; c++) acc += __ldg(wr + c) * __ldg(wl + c);
    V[k * 4 + j] = acc;
}

// ---------------------------------------------------------------------------
// y2[i,:4] = relu(h[i,:]) @ V; also zeroes c[i,:4]. One warp per node.
// ---------------------------------------------------------------------------
__global__ __launch_bounds__(256) void y2_kernel(
    const float* __restrict__ h, const float* __restrict__ V,
    float* __restrict__ y2, float* __restrict__ c, int n)
{
    __shared__ float VT[4][HID];   // transposed: VT[j][k]
    for (int i = threadIdx.x; i < 512; i += 256)
        VT[i & 3][i >> 2] = __ldg(V + i);
    __syncthreads();

    int warp = (int)(((long long)blockIdx.x * blockDim.x + threadIdx.x) >> 5);
    int lane = threadIdx.x & 31;
    if (warp >= n) return;

    float4 hv = __ldg((const float4*)(h + (size_t)warp * HID) + lane);
    hv.x = fmaxf(hv.x, 0.f); hv.y = fmaxf(hv.y, 0.f);
    hv.z = fmaxf(hv.z, 0.f); hv.w = fmaxf(hv.w, 0.f);

    float a[4];
#pragma unroll
    for (int j = 0; j < 4; j++) {
        float4 v = *(const float4*)&VT[j][lane * 4];
        a[j] = hv.x * v.x + hv.y * v.y + hv.z * v.z + hv.w * v.w;
    }
#pragma unroll
    for (int o = 16; o > 0; o >>= 1) {
#pragma unroll
        for (int j = 0; j < 4; j++)
            a[j] += __shfl_xor_sync(0xFFFFFFFFu, a[j], o);
    }
    if (lane == 0) {
        ((float4*)y2)[warp] = make_float4(a[0], a[1], a[2], a[3]);
        ((float4*)c)[warp]  = make_float4(0.f, 0.f, 0.f, 0.f);
    }
}

// ---------------------------------------------------------------------------
// Narrow scatter (layer 2 collapsed): c[dst] += w_e * y2[src]. 4 edges/thread.
// ---------------------------------------------------------------------------
__global__ __launch_bounds__(256) void scatter4_kernel(
    const float* __restrict__ y2, const int* __restrict__ ei,
    const float* __restrict__ ew, float* __restrict__ c, int E)
{
    int tI = blockIdx.x * blockDim.x + threadIdx.x;
    int e0 = tI * 4;
    if (e0 >= E) return;

    if (e0 + 4 <= E) {
        int4   s4 = __ldg((const int4*)ei + tI);
        int4   d4 = __ldg((const int4*)(ei + E) + tI);
        float4 w4 = __ldg((const float4*)ew + tI);
        int   s[4] = {s4.x, s4.y, s4.z, s4.w};
        int   d[4] = {d4.x, d4.y, d4.z, d4.w};
        float w[4] = {w4.x, w4.y, w4.z, w4.w};
        float4 v[4];
#pragma unroll
        for (int j = 0; j < 4; j++) v[j] = __ldg((const float4*)y2 + s[j]);
#pragma unroll
        for (int j = 0; j < 4; j++) {
            v[j].x *= w[j]; v[j].y *= w[j]; v[j].z *= w[j]; v[j].w *= w[j];
            float* p = c + (size_t)d[j] * 4;
            asm volatile("red.global.add.v4.f32 [%0], {%1,%2,%3,%4};"
                         :: "l"(p), "f"(v[j].x), "f"(v[j].y), "f"(v[j].z), "f"(v[j].w)
                         : "memory");
        }
    } else {
        for (int e = e0; e < E; e++) {
            int   s = __ldg(ei + e);
            int   d = __ldg(ei + E + e);
            float w = __ldg(ew + e);
            float4 v = __ldg((const float4*)y2 + s);
            v.x *= w; v.y *= w; v.z *= w; v.w *= w;
            float* p = c + (size_t)d * 4;
            asm volatile("red.global.add.v4.f32 [%0], {%1,%2,%3,%4};"
                         :: "l"(p), "f"(v.x), "f"(v.y), "f"(v.z), "f"(v.w) : "memory");
        }
    }
}

// ---------------------------------------------------------------------------
// Pair epilogue (collapsed): out[p] = (c[a].0 + c[b].1, c[a].2 + c[b].3)
// ---------------------------------------------------------------------------
__global__ __launch_bounds__(256) void pair_small_kernel(
    const float* __restrict__ c, const int* __restrict__ pe,
    float* __restrict__ out, int P)
{
    int p = blockIdx.x * blockDim.x + threadIdx.x;
    if (p >= P) return;
    int a = __ldg(pe + p);
    int b = __ldg(pe + P + p);
    float4 ca = __ldg((const float4*)c + a);
    float4 cb = __ldg((const float4*)c + b);
    ((float2*)out)[p] = make_float2(ca.x + cb.y, ca.z + cb.w);
}

// ---------------------------------------------------------------------------
// Launch
// ---------------------------------------------------------------------------
extern "C" void kernel_launch(void* const* d_in, const int* in_sizes, int n_in,
                              void* d_out, int out_size)
{
    const float* x    = (const float*)d_in[0];
    const int*   ei1  = (const int*)  d_in[1];
    const int*   ei2  = (const int*)  d_in[2];
    const float* ew1  = (const float*)d_in[3];
    const float* ew2  = (const float*)d_in[4];
    const int*   pe   = (const int*)  d_in[5];
    const float* W1   = (const float*)d_in[6];
    const float* W2   = (const float*)d_in[7];
    const float* Wlin = (const float*)d_in[8];
    float* out = (float*)d_out;

    int n  = in_sizes[0] / HID;
    int E1 = in_sizes[3];
    int E2 = in_sizes[4];
    int P  = in_sizes[5] / 2;

    void *p_buf0, *p_h, *p_y2, *p_c, *p_V;
    cudaGetSymbolAddress(&p_buf0, g_buf0);
    cudaGetSymbolAddress(&p_h,    g_h);
    cudaGetSymbolAddress(&p_y2,   g_y2);
    cudaGetSymbolAddress(&p_c,    g_c);
    cudaGetSymbolAddress(&p_V,    g_V);
    float* buf0 = (float*)p_buf0;
    float* h    = (float*)p_h;
    float* y2   = (float*)p_y2;
    float* c    = (float*)p_c;
    float* V    = (float*)p_V;

    cudaFuncSetAttribute(gemm_mma_kernel,
        cudaFuncAttributeMaxDynamicSharedMemorySize, GEMM_SMEM_BYTES);

    // V = W2 @ WlinPacked  (independent of everything up to y2_kernel)
    vpack_kernel<<<1, 512>>>(W2, Wlin, V);

    // Layer 1: buf0 = x @ W1 (also zeroes h) ; h = scatter-add
    int gemmBlocks = (n + 63) / 64;
    gemm_mma_kernel<<<gemmBlocks, 256, GEMM_SMEM_BYTES>>>(x, W1, buf0, h, n);
    {
        int warps = (E1 + 7) / 8;
        int blocks = (warps * 32 + 255) / 256;
        scatter_kernel<<<blocks, 256>>>(buf0, ei1, ew1, h, E1);
    }

    // Collapsed layer 2: y2 = relu(h) @ V (zeroes c); c = narrow scatter-add
    {
        int blocks = (n * 32 + 255) / 256;
        y2_kernel<<<blocks, 256>>>(h, V, y2, c, n);
    }
    {
        int threads = (E2 + 3) / 4;
        int blocks = (threads + 255) / 256;
        scatter4_kernel<<<blocks, 256>>>(y2, ei2, ew2, c, E2);
    }

    // Pair epilogue
    pair_small_kernel<<<(P + 255) / 256, 256>>>(c, pe, out, P);
}

// round 8
// speedup vs baseline: 2.8086x; 1.0753x over previous
#include <cuda_runtime.h>
#include <cuda_bf16.h>
#include <cstdint>

#define HID 128
#define NMAX 100000

__device__ float  g_buf0[(size_t)NMAX * HID];  // xw1
__device__ float  g_h   [(size_t)NMAX * HID];  // layer-1 aggregate
__device__ float  g_y2  [(size_t)NMAX * 4];    // relu(h) @ V
__device__ float  g_c   [(size_t)NMAX * 4];    // layer-2 collapsed aggregate
__device__ float  g_VT  [4 * HID];             // (W2 @ WlinPacked)^T : VT[j][k]
__device__ ushort g_Whi [128 * 136];           // W1 hi, padded [k][n] layout
__device__ ushort g_Wlo [128 * 136];           // W1 lo

__device__ __forceinline__ uint32_t smem_u32(const void* p) {
    uint32_t a;
    asm("{ .reg .u64 t; cvta.to.shared.u64 t, %1; cvt.u32.u64 %0, t; }"
        : "=r"(a) : "l"(p));
    return a;
}

#define LDM_X4(r0, r1, r2, r3, a)                                             \
    asm volatile("ldmatrix.sync.aligned.m8n8.x4.shared.b16 {%0,%1,%2,%3}, [%4];" \
                 : "=r"(r0), "=r"(r1), "=r"(r2), "=r"(r3) : "r"(a))
#define LDM_X4T(r0, r1, r2, r3, a)                                            \
    asm volatile("ldmatrix.sync.aligned.m8n8.x4.trans.shared.b16 {%0,%1,%2,%3}, [%4];" \
                 : "=r"(r0), "=r"(r1), "=r"(r2), "=r"(r3) : "r"(a))
#define MMA_BF16(d, a, b)                                                     \
    asm volatile("mma.sync.aligned.m16n8k16.row.col.f32.bf16.bf16.f32 "       \
                 "{%0,%1,%2,%3}, {%4,%5,%6,%7}, {%8,%9}, {%0,%1,%2,%3};"      \
                 : "+f"((d)[0]), "+f"((d)[1]), "+f"((d)[2]), "+f"((d)[3])     \
                 : "r"((a)[0]), "r"((a)[1]), "r"((a)[2]), "r"((a)[3]),        \
                   "r"((b)[0]), "r"((b)[1]))

// Cheap hi/lo split: hi = truncate-to-bf16 (exact prefix), lo = rn(f - hi).
__device__ __forceinline__ void split2(float f, ushort& h, ushort& l) {
    uint32_t fb = __float_as_uint(f);
    h = (ushort)(fb >> 16);
    float lo = f - __uint_as_float(fb & 0xFFFF0000u);   // exact
    __nv_bfloat16 bl = __float2bfloat16_rn(lo);
    l = *(ushort*)&bl;
}

// ---------------------------------------------------------------------------
// Pre-split W1 into bf16 hi/lo, padded [k][136] layout (matches gemm smem).
// ---------------------------------------------------------------------------
__global__ void wsplit_kernel(const float* __restrict__ W,
                              ushort* __restrict__ Whi, ushort* __restrict__ Wlo)
{
    int i = blockIdx.x * blockDim.x + threadIdx.x;   // 0..4095
    if (i >= 128 * 32) return;
    int k = i >> 5, q = i & 31;
    float4 v = __ldg((const float4*)(W + (size_t)k * HID) + q);
    float f[4] = {v.x, v.y, v.z, v.w};
    ushort h[4], l[4];
#pragma unroll
    for (int j = 0; j < 4; j++) split2(f[j], h[j], l[j]);
    uint2 hp = make_uint2((uint32_t)h[0] | ((uint32_t)h[1] << 16),
                          (uint32_t)h[2] | ((uint32_t)h[3] << 16));
    uint2 lp = make_uint2((uint32_t)l[0] | ((uint32_t)l[1] << 16),
                          (uint32_t)l[2] | ((uint32_t)l[3] << 16));
    *(uint2*)(Whi + (size_t)k * 136 + q * 4) = hp;
    *(uint2*)(Wlo + (size_t)k * 136 + q * 4) = lp;
}

// ===========================================================================
// GEMM1 (HMMA bf16x3): Y[n,128] = X @ W1; also zeroes Zero rows.
// CTA: 64x128 tile, 8 warps (2m x 4n), warp tile 32x32. 2 CTAs/SM.
// W arrives pre-split (bf16 hi/lo) — staging is a pure uint4 copy.
// ===========================================================================
#define LDS_ 136
#define OFF_XH 0
#define OFF_XL (64 * LDS_ * 2)
#define OFF_WH (2 * 64 * LDS_ * 2)
#define OFF_WL (OFF_WH + 128 * LDS_ * 2)
#define GEMM_SMEM_BYTES (OFF_WL + 128 * LDS_ * 2)   // 104,448 B
#define W_U4 (128 * LDS_ * 2 / 16)                  // 2176 uint4 per array

__global__ __launch_bounds__(256, 2) void gemm_mma_kernel(
    const float* __restrict__ X,
    const ushort* __restrict__ Whi, const ushort* __restrict__ Wlo,
    float* __restrict__ Y, float* __restrict__ Zero, int n)
{
    extern __shared__ char sm[];
    const int t   = threadIdx.x;
    const int lid = t & 31;
    const int wid = t >> 5;
    const int row0 = blockIdx.x * 64;

    // ---- Zero pass (replaces cudaMemset of the aggregate buffer)
    {
        float4 z4 = make_float4(0.f, 0.f, 0.f, 0.f);
        for (int i = t; i < 64 * 32; i += 256) {
            int m = i >> 5, q = i & 31;
            int r = row0 + m;
            if (r < n) ((float4*)(Zero + (size_t)r * HID))[q] = z4;
        }
    }

    // ---- Stage W (pre-split): straight uint4 copies
    {
        const uint4* wh4 = (const uint4*)Whi;
        const uint4* wl4 = (const uint4*)Wlo;
        uint4* dh = (uint4*)(sm + OFF_WH);
        uint4* dl = (uint4*)(sm + OFF_WL);
        for (int i = t; i < W_U4; i += 256) {
            dh[i] = __ldg(wh4 + i);
            dl[i] = __ldg(wl4 + i);
        }
    }

    // ---- Stage X tile split hi/lo
    for (int i = t; i < 64 * 32; i += 256) {
        int m = i >> 5, q = i & 31;
        int r = row0 + m;
        int rc = r < n ? r : 0;
        float4 v = __ldg((const float4*)(X + (size_t)rc * HID) + q);
        float f[4] = {v.x, v.y, v.z, v.w};
        ushort h[4], l[4];
#pragma unroll
        for (int j = 0; j < 4; j++) split2(f[j], h[j], l[j]);
        uint2 hp = make_uint2((uint32_t)h[0] | ((uint32_t)h[1] << 16),
                              (uint32_t)h[2] | ((uint32_t)h[3] << 16));
        uint2 lp = make_uint2((uint32_t)l[0] | ((uint32_t)l[1] << 16),
                              (uint32_t)l[2] | ((uint32_t)l[3] << 16));
        size_t off = ((size_t)m * LDS_ + q * 4) * 2;
        *(uint2*)(sm + OFF_XH + off) = hp;
        *(uint2*)(sm + OFF_XL + off) = lp;
    }
    __syncthreads();

    const int wm = wid & 1;
    const int wn = wid >> 1;
    const int mat  = lid >> 3;
    const int rsel = (mat & 1) * 8 + (lid & 7);
    const int csel = (mat >> 1) * 8;

    const uint32_t sb = smem_u32(sm);
    uint32_t aH = sb + OFF_XH + (uint32_t)(((wm * 32 + rsel) * LDS_ + csel) * 2);
    uint32_t aL = aH + (OFF_XL - OFF_XH);
    uint32_t bH = sb + OFF_WH + (uint32_t)((rsel * LDS_ + wn * 32 + csel) * 2);
    uint32_t bL = bH + (OFF_WL - OFF_WH);

    float acc[2][4][4];
#pragma unroll
    for (int mi = 0; mi < 2; mi++)
#pragma unroll
        for (int nj = 0; nj < 4; nj++)
#pragma unroll
            for (int e = 0; e < 4; e++) acc[mi][nj][e] = 0.f;

#pragma unroll
    for (int ks = 0; ks < 8; ks++) {
        const uint32_t ao = ks * 32;
        const uint32_t bo = (uint32_t)(ks * 16 * LDS_ * 2);

        uint32_t ah[2][4], al[2][4];
        LDM_X4(ah[0][0], ah[0][1], ah[0][2], ah[0][3], aH + ao);
        LDM_X4(ah[1][0], ah[1][1], ah[1][2], ah[1][3], aH + ao + 16 * LDS_ * 2);
        LDM_X4(al[0][0], al[0][1], al[0][2], al[0][3], aL + ao);
        LDM_X4(al[1][0], al[1][1], al[1][2], al[1][3], aL + ao + 16 * LDS_ * 2);

        uint32_t bh[4][2], bl[4][2];
#pragma unroll
        for (int g = 0; g < 2; g++) {
            LDM_X4T(bh[g * 2][0], bh[g * 2][1], bh[g * 2 + 1][0], bh[g * 2 + 1][1],
                    bH + bo + g * 32);
            LDM_X4T(bl[g * 2][0], bl[g * 2][1], bl[g * 2 + 1][0], bl[g * 2 + 1][1],
                    bL + bo + g * 32);
        }

#pragma unroll
        for (int mi = 0; mi < 2; mi++)
#pragma unroll
            for (int nj = 0; nj < 4; nj++) {
                MMA_BF16(acc[mi][nj], ah[mi], bh[nj]);
                MMA_BF16(acc[mi][nj], ah[mi], bl[nj]);
                MMA_BF16(acc[mi][nj], al[mi], bh[nj]);
            }
    }

    const int g  = lid >> 2;
    const int c2 = (lid & 3) * 2;
#pragma unroll
    for (int mi = 0; mi < 2; mi++) {
        int rbase = row0 + wm * 32 + mi * 16;
        int r1 = rbase + g, r2 = rbase + g + 8;
#pragma unroll
        for (int nj = 0; nj < 4; nj++) {
            int col = wn * 32 + nj * 8 + c2;
            if (r1 < n)
                *(float2*)(Y + (size_t)r1 * HID + col) =
                    make_float2(acc[mi][nj][0], acc[mi][nj][1]);
            if (r2 < n)
                *(float2*)(Y + (size_t)r2 * HID + col) =
                    make_float2(acc[mi][nj][2], acc[mi][nj][3]);
        }
    }
}

// ---------------------------------------------------------------------------
// Scatter (wide, layer 1): out[dst] += w_e * F[src]. One warp per 8 edges.
// ---------------------------------------------------------------------------
__global__ __launch_bounds__(256) void scatter_kernel(
    const float* __restrict__ F, const int* __restrict__ ei,
    const float* __restrict__ ew, float* __restrict__ out, int E)
{
    int warp = (int)(((long long)blockIdx.x * blockDim.x + threadIdx.x) >> 5);
    int lane = threadIdx.x & 31;
    int e0 = warp * 8;
    if (e0 >= E) return;

    if (e0 + 8 <= E) {
        int q = e0 >> 2;
        int4   sa = __ldg((const int4*)ei + q);
        int4   sb = __ldg((const int4*)ei + q + 1);
        int4   da = __ldg((const int4*)(ei + E) + q);
        int4   db = __ldg((const int4*)(ei + E) + q + 1);
        float4 wa = __ldg((const float4*)ew + q);
        float4 wb = __ldg((const float4*)ew + q + 1);

        int   s[8] = {sa.x, sa.y, sa.z, sa.w, sb.x, sb.y, sb.z, sb.w};
        int   d[8] = {da.x, da.y, da.z, da.w, db.x, db.y, db.z, db.w};
        float w[8] = {wa.x, wa.y, wa.z, wa.w, wb.x, wb.y, wb.z, wb.w};

        float4 v[8];
#pragma unroll
        for (int j = 0; j < 8; j++)
            v[j] = __ldg((const float4*)(F + (size_t)s[j] * HID) + lane);
#pragma unroll
        for (int j = 0; j < 8; j++) {
            v[j].x *= w[j]; v[j].y *= w[j]; v[j].z *= w[j]; v[j].w *= w[j];
            float* p = out + (size_t)d[j] * HID + lane * 4;
            asm volatile("red.global.add.v4.f32 [%0], {%1,%2,%3,%4};"
                         :: "l"(p), "f"(v[j].x), "f"(v[j].y), "f"(v[j].z), "f"(v[j].w)
                         : "memory");
        }
    } else {
        for (int e = e0; e < E; e++) {
            int   s = __ldg(ei + e);
            int   d = __ldg(ei + E + e);
            float w = __ldg(ew + e);
            float4 v = __ldg((const float4*)(F + (size_t)s * HID) + lane);
            v.x *= w; v.y *= w; v.z *= w; v.w *= w;
            float* p = out + (size_t)d * HID + lane * 4;
            asm volatile("red.global.add.v4.f32 [%0], {%1,%2,%3,%4};"
                         :: "l"(p), "f"(v.x), "f"(v.y), "f"(v.z), "f"(v.w) : "memory");
        }
    }
}

// ---------------------------------------------------------------------------
// VT[j][k] = sum_c W2[k,c] * wl_j[c]  (transposed for contiguous y2 loads)
// wl_0 = Wlin[0,0:128], wl_1 = Wlin[0,128:256], wl_2 = Wlin[1,0:128],
// wl_3 = Wlin[1,128:256].
// ---------------------------------------------------------------------------
__global__ void vpack_kernel(const float* __restrict__ W2,
                             const float* __restrict__ Wlin,
                             float* __restrict__ VT)
{
    int i = threadIdx.x;          // 0..511
    int k = i >> 2, j = i & 3;
    const float* wl = Wlin + (j >> 1) * 256 + (j & 1) * 128;
    const float* wr = W2 + (size_t)k * HID;
    float acc = 0.f;
#pragma unroll 8
    for (int c = 0; c < HID; c++) acc += __ldg(wr + c) * __ldg(wl + c);
    VT[j * HID + k] = acc;
}

// ---------------------------------------------------------------------------
// y2[i,:4] = relu(h[i,:]) @ V; also zeroes c[i,:4].
// Lane specialization: lane = (chunk 0..7, j 0..3); 16-float partial dot,
// 3 shuffle steps across chunks. V in registers, grid-stride over nodes.
// ---------------------------------------------------------------------------
__global__ __launch_bounds__(256) void y2_kernel(
    const float* __restrict__ h, const float* __restrict__ VT,
    float* __restrict__ y2, float* __restrict__ c, int n)
{
    int gw   = (int)(((long long)blockIdx.x * blockDim.x + threadIdx.x) >> 5);
    int nw   = (int)(((long long)gridDim.x * blockDim.x) >> 5);
    int lane = threadIdx.x & 31;
    int chunk = lane >> 2, j = lane & 3;

    float4 vv[4];
#pragma unroll
    for (int g = 0; g < 4; g++)
        vv[g] = __ldg((const float4*)(VT + j * HID + chunk * 16) + g);

    for (int node = gw; node < n; node += nw) {
        const float4* hr = (const float4*)(h + (size_t)node * HID) + chunk * 4;
        float4 hv[4];
#pragma unroll
        for (int g = 0; g < 4; g++) hv[g] = __ldg(hr + g);
        float acc = 0.f;
#pragma unroll
        for (int g = 0; g < 4; g++) {
            float x0 = fmaxf(hv[g].x, 0.f), x1 = fmaxf(hv[g].y, 0.f);
            float x2 = fmaxf(hv[g].z, 0.f), x3 = fmaxf(hv[g].w, 0.f);
            acc += x0 * vv[g].x + x1 * vv[g].y + x2 * vv[g].z + x3 * vv[g].w;
        }
        acc += __shfl_xor_sync(0xFFFFFFFFu, acc, 4);
        acc += __shfl_xor_sync(0xFFFFFFFFu, acc, 8);
        acc += __shfl_xor_sync(0xFFFFFFFFu, acc, 16);
        if (lane < 4)      y2[(size_t)node * 4 + j] = acc;
        else if (lane < 8) c [(size_t)node * 4 + j] = 0.f;
    }
}

// ---------------------------------------------------------------------------
// Narrow scatter (layer 2 collapsed): c[dst] += w_e * y2[src]. 4 edges/thread.
// ---------------------------------------------------------------------------
__global__ __launch_bounds__(256) void scatter4_kernel(
    const float* __restrict__ y2, const int* __restrict__ ei,
    const float* __restrict__ ew, float* __restrict__ c, int E)
{
    int tI = blockIdx.x * blockDim.x + threadIdx.x;
    int e0 = tI * 4;
    if (e0 >= E) return;

    if (e0 + 4 <= E) {
        int4   s4 = __ldg((const int4*)ei + tI);
        int4   d4 = __ldg((const int4*)(ei + E) + tI);
        float4 w4 = __ldg((const float4*)ew + tI);
        int   s[4] = {s4.x, s4.y, s4.z, s4.w};
        int   d[4] = {d4.x, d4.y, d4.z, d4.w};
        float w[4] = {w4.x, w4.y, w4.z, w4.w};
        float4 v[4];
#pragma unroll
        for (int j = 0; j < 4; j++) v[j] = __ldg((const float4*)y2 + s[j]);
#pragma unroll
        for (int j = 0; j < 4; j++) {
            v[j].x *= w[j]; v[j].y *= w[j]; v[j].z *= w[j]; v[j].w *= w[j];
            float* p = c + (size_t)d[j] * 4;
            asm volatile("red.global.add.v4.f32 [%0], {%1,%2,%3,%4};"
                         :: "l"(p), "f"(v[j].x), "f"(v[j].y), "f"(v[j].z), "f"(v[j].w)
                         : "memory");
        }
    } else {
        for (int e = e0; e < E; e++) {
            int   s = __ldg(ei + e);
            int   d = __ldg(ei + E + e);
            float w = __ldg(ew + e);
            float4 v = __ldg((const float4*)y2 + s);
            v.x *= w; v.y *= w; v.z *= w; v.w *= w;
            float* p = c + (size_t)d * 4;
            asm volatile("red.global.add.v4.f32 [%0], {%1,%2,%3,%4};"
                         :: "l"(p), "f"(v.x), "f"(v.y), "f"(v.z), "f"(v.w) : "memory");
        }
    }
}

// ---------------------------------------------------------------------------
// Pair epilogue (collapsed): out[p] = (c[a].0 + c[b].1, c[a].2 + c[b].3)
// ---------------------------------------------------------------------------
__global__ __launch_bounds__(256) void pair_small_kernel(
    const float* __restrict__ c, const int* __restrict__ pe,
    float* __restrict__ out, int P)
{
    int p = blockIdx.x * blockDim.x + threadIdx.x;
    if (p >= P) return;
    int a = __ldg(pe + p);
    int b = __ldg(pe + P + p);
    float4 ca = __ldg((const float4*)c + a);
    float4 cb = __ldg((const float4*)c + b);
    ((float2*)out)[p] = make_float2(ca.x + cb.y, ca.z + cb.w);
}

// ---------------------------------------------------------------------------
// Launch
// ---------------------------------------------------------------------------
extern "C" void kernel_launch(void* const* d_in, const int* in_sizes, int n_in,
                              void* d_out, int out_size)
{
    const float* x    = (const float*)d_in[0];
    const int*   ei1  = (const int*)  d_in[1];
    const int*   ei2  = (const int*)  d_in[2];
    const float* ew1  = (const float*)d_in[3];
    const float* ew2  = (const float*)d_in[4];
    const int*   pe   = (const int*)  d_in[5];
    const float* W1   = (const float*)d_in[6];
    const float* W2   = (const float*)d_in[7];
    const float* Wlin = (const float*)d_in[8];
    float* out = (float*)d_out;

    int n  = in_sizes[0] / HID;
    int E1 = in_sizes[3];
    int E2 = in_sizes[4];
    int P  = in_sizes[5] / 2;

    void *p_buf0, *p_h, *p_y2, *p_c, *p_VT, *p_Whi, *p_Wlo;
    cudaGetSymbolAddress(&p_buf0, g_buf0);
    cudaGetSymbolAddress(&p_h,    g_h);
    cudaGetSymbolAddress(&p_y2,   g_y2);
    cudaGetSymbolAddress(&p_c,    g_c);
    cudaGetSymbolAddress(&p_VT,   g_VT);
    cudaGetSymbolAddress(&p_Whi,  g_Whi);
    cudaGetSymbolAddress(&p_Wlo,  g_Wlo);
    float*  buf0 = (float*)p_buf0;
    float*  h    = (float*)p_h;
    float*  y2   = (float*)p_y2;
    float*  c    = (float*)p_c;
    float*  VT   = (float*)p_VT;
    ushort* Whi  = (ushort*)p_Whi;
    ushort* Wlo  = (ushort*)p_Wlo;

    cudaFuncSetAttribute(gemm_mma_kernel,
        cudaFuncAttributeMaxDynamicSharedMemorySize, GEMM_SMEM_BYTES);

    // Tiny precomputes (serial but ~2-3 us total)
    wsplit_kernel<<<16, 256>>>(W1, Whi, Wlo);
    vpack_kernel<<<1, 512>>>(W2, Wlin, VT);

    // Layer 1: buf0 = x @ W1 (also zeroes h) ; h = scatter-add
    int gemmBlocks = (n + 63) / 64;
    gemm_mma_kernel<<<gemmBlocks, 256, GEMM_SMEM_BYTES>>>(x, Whi, Wlo, buf0, h, n);
    {
        int warps = (E1 + 7) / 8;
        int blocks = (warps * 32 + 255) / 256;
        scatter_kernel<<<blocks, 256>>>(buf0, ei1, ew1, h, E1);
    }

    // Collapsed layer 2: y2 = relu(h) @ V (zeroes c); c = narrow scatter-add
    y2_kernel<<<1184, 256>>>(h, VT, y2, c, n);
    {
        int threads = (E2 + 3) / 4;
        int blocks = (threads + 255) / 256;
        scatter4_kernel<<<blocks, 256>>>(y2, ei2, ew2, c, E2);
    }

    // Pair epilogue
    pair_small_kernel<<<(P + 255) / 256, 256>>>(c, pe, out, P);
}